// round 10
// baseline (speedup 1.0000x reference)
#include <cuda_runtime.h>
#include <cuda_bf16.h>
#include <cstdint>
#include <math.h>

// Problem dims
#define BB 4
#define TT 3072
#define DD 1024
#define HH 16
#define HD 64
#define TC 1024          // conv outputs per batch
#define TKK 1025         // k_tmp rows per batch

// ---------------- static scratch ----------------
__device__ __nv_bfloat16 g_xhi[BB * TT * DD], g_xlo[BB * TT * DD];
__device__ __nv_bfloat16 g_wqhi[DD * DD], g_wqlo[DD * DD];
__device__ __nv_bfloat16 g_wkhi[DD * DD], g_wklo[DD * DD];
__device__ __nv_bfloat16 g_wvhi[DD * DD], g_wvlo[DD * DD];
__device__ __nv_bfloat16 g_wohi[DD * DD], g_wolo[DD * DD];
__device__ __nv_bfloat16 g_wchi[DD * 3 * DD], g_wclo[DD * 3 * DD];
__device__ __nv_bfloat16 g_khi2[BB * TKK * DD], g_klo2[BB * TKK * DD];  // k_tmp hi/lo
__device__ __nv_bfloat16 g_qhi[BB * TT * DD], g_qlo[BB * TT * DD];      // Q (pre-scaled)
__device__ __nv_bfloat16 g_kbhi[BB * TKK * DD], g_kblo[BB * TKK * DD];  // K proj
__device__ __nv_bfloat16 g_vbhi[BB * TKK * DD], g_vblo[BB * TKK * DD];  // V proj
__device__ __nv_bfloat16 g_ohi[BB * TT * DD], g_olo[BB * TT * DD];      // attn out

// ---------------- helpers ----------------
__device__ __forceinline__ uint32_t smem_u32(const void* p) {
    uint32_t a;
    asm("{ .reg .u64 t; cvta.to.shared.u64 t, %1; cvt.u32.u64 %0, t; }" : "=r"(a) : "l"(p));
    return a;
}
__device__ __forceinline__ void ldsm4(uint32_t* r, uint32_t addr) {
    asm volatile("ldmatrix.sync.aligned.m8n8.x4.shared.b16 {%0,%1,%2,%3}, [%4];"
        : "=r"(r[0]), "=r"(r[1]), "=r"(r[2]), "=r"(r[3]) : "r"(addr));
}
__device__ __forceinline__ void ldsm4t(uint32_t* r, uint32_t addr) {
    asm volatile("ldmatrix.sync.aligned.m8n8.x4.trans.shared.b16 {%0,%1,%2,%3}, [%4];"
        : "=r"(r[0]), "=r"(r[1]), "=r"(r[2]), "=r"(r[3]) : "r"(addr));
}
__device__ __forceinline__ void mma16816(float* c, const uint32_t* a, uint32_t b0, uint32_t b1) {
    asm volatile("mma.sync.aligned.m16n8k16.row.col.f32.bf16.bf16.f32 "
        "{%0,%1,%2,%3}, {%4,%5,%6,%7}, {%8,%9}, {%0,%1,%2,%3};"
        : "+f"(c[0]), "+f"(c[1]), "+f"(c[2]), "+f"(c[3])
        : "r"(a[0]), "r"(a[1]), "r"(a[2]), "r"(a[3]), "r"(b0), "r"(b1));
}
__device__ __forceinline__ uint32_t packbf2(float x, float y) {
    uint32_t lo = __bfloat16_as_ushort(__float2bfloat16(x));
    uint32_t hi = __bfloat16_as_ushort(__float2bfloat16(y));
    return lo | (hi << 16);
}

// ---------------- split / repack kernels ----------------
__global__ void split_kernel(const float* __restrict__ s, __nv_bfloat16* __restrict__ hi,
                             __nv_bfloat16* __restrict__ lo, int n) {
    int i = blockIdx.x * 256 + threadIdx.x;
    if (i >= n) return;
    float v = s[i];
    __nv_bfloat16 h = __float2bfloat16(v);
    hi[i] = h;
    lo[i] = __float2bfloat16(v - __bfloat162float(h));
}
// 4 weight matrices (each DD*DD = 1<<20 elems) in one launch
__global__ void split4_kernel(const float* __restrict__ w0, const float* __restrict__ w1,
                              const float* __restrict__ w2, const float* __restrict__ w3,
                              __nv_bfloat16* __restrict__ h0, __nv_bfloat16* __restrict__ l0,
                              __nv_bfloat16* __restrict__ h1, __nv_bfloat16* __restrict__ l1,
                              __nv_bfloat16* __restrict__ h2, __nv_bfloat16* __restrict__ l2,
                              __nv_bfloat16* __restrict__ h3, __nv_bfloat16* __restrict__ l3) {
    int i = blockIdx.x * 256 + threadIdx.x;
    int w = i >> 20, j = i & ((1 << 20) - 1);
    const float* s = (w == 0) ? w0 : (w == 1) ? w1 : (w == 2) ? w2 : w3;
    __nv_bfloat16* hp = (w == 0) ? h0 : (w == 1) ? h1 : (w == 2) ? h2 : h3;
    __nv_bfloat16* lp = (w == 0) ? l0 : (w == 1) ? l1 : (w == 2) ? l2 : l3;
    float v = s[j];
    __nv_bfloat16 h = __float2bfloat16(v);
    hp[j] = h;
    lp[j] = __float2bfloat16(v - __bfloat162float(h));
}
__global__ void repack_conv_kernel(const float* __restrict__ W, __nv_bfloat16* __restrict__ hi,
                                   __nv_bfloat16* __restrict__ lo) {
    int idx = blockIdx.x * 256 + threadIdx.x;
    if (idx >= DD * DD * 3) return;
    int o = idx / (DD * 3);
    int r = idx % (DD * 3);
    int i = r / 3, kw = r % 3;
    float v = W[idx];
    __nv_bfloat16 h = __float2bfloat16(v);
    long d = (long)o * (3 * DD) + kw * DD + i;
    hi[d] = h;
    lo[d] = __float2bfloat16(v - __bfloat162float(h));
}
__global__ void copy_row0_kernel(const float* __restrict__ x, __nv_bfloat16* __restrict__ khi,
                                 __nv_bfloat16* __restrict__ klo) {
    int idx = blockIdx.x * 256 + threadIdx.x;
    if (idx >= BB * DD) return;
    int b = idx / DD, i = idx % DD;
    float v = x[(long)b * TT * DD + i];
    __nv_bfloat16 h = __float2bfloat16(v);
    long d = (long)b * TKK * DD + i;
    khi[d] = h;
    klo[d] = __float2bfloat16(v - __bfloat162float(h));
}

// ---------------- mma.sync GEMM: C[M,1024] = A @ B^T (bf16x3 split) ----------------
// outmap 0: fp32 Cf (+bias).  outmap 1: conv scatter -> bf16 hi/lo.  outmap 2: bf16 hi/lo (scaled).
// blockIdx.z==1 selects the secondary B/C pointers (fused K/V launch).
#define GM_BM 128
#define GM_BN 128
#define GM_BK 32
#define GM_ROWB 80
#define GM_TILE (128 * GM_ROWB)        // 10240
#define GM_STAGE (4 * GM_TILE)         // 40960
#define GM_NS 3
#define GM_SMEM (GM_NS * GM_STAGE)     // 122880

__global__ void __launch_bounds__(256)
gemm_mma(const __nv_bfloat16* Ahi, const __nv_bfloat16* Alo, long lda,
         const __nv_bfloat16* Bhi, const __nv_bfloat16* Blo,
         const __nv_bfloat16* Bhi2, const __nv_bfloat16* Blo2,
         const float* bias,
         float* Cf, __nv_bfloat16* Chi, __nv_bfloat16* Clo,
         __nv_bfloat16* Chi2, __nv_bfloat16* Clo2,
         int M, int K, int outmap, float oscale)
{
    if (blockIdx.z == 1) { Bhi = Bhi2; Blo = Blo2; Chi = Chi2; Clo = Clo2; }
    extern __shared__ char smem[];
    const uint32_t sb = smem_u32(smem);
    const int tid = threadIdx.x;
    const int wid = tid >> 5, lane = tid & 31;
    const int bm = blockIdx.y * GM_BM, bn = blockIdx.x * GM_BN;
    const int mbase = (wid & 3) * 32;
    const int nbase = (wid >> 2) * 64;

    const int grp = lane >> 3, rowg = lane & 7;
    const int a_row = (grp & 1) * 8 + rowg;
    const int a_koff = (grp >> 1) * 16;
    const int b_row = (grp >> 1) * 8 + rowg;
    const int b_koff = (grp & 1) * 16;

    float acc[2][8][4];
#pragma unroll
    for (int i = 0; i < 2; i++)
#pragma unroll
        for (int j = 0; j < 8; j++)
#pragma unroll
            for (int k = 0; k < 4; k++) acc[i][j][k] = 0.f;

    auto load_stage = [&](int stg, int c) {
        const uint32_t base = sb + stg * GM_STAGE;
        const int k0 = c * GM_BK;
#pragma unroll
        for (int it = 0; it < 8; it++) {
            int i = it * 256 + tid;
            int t = i >> 9;               // 0 Ahi, 1 Alo, 2 Bhi, 3 Blo
            int r = (i >> 2) & 127;
            int s = i & 3;
            const __nv_bfloat16* sp;
            int sz = 16;
            if (t < 2) {
                int row = bm + r;
                if (row >= M) { row = bm; sz = 0; }
                sp = (t ? Alo : Ahi) + (long)row * lda + k0 + s * 8;
            } else {
                sp = ((t == 3) ? Blo : Bhi) + (long)(bn + r) * K + k0 + s * 8;
            }
            uint32_t dp = base + (uint32_t)(t * GM_TILE + r * GM_ROWB + s * 16);
            asm volatile("cp.async.cg.shared.global [%0], [%1], 16, %2;"
                         :: "r"(dp), "l"(sp), "r"(sz));
        }
        asm volatile("cp.async.commit_group;" ::: "memory");
    };

    const int nch = K / GM_BK;
#pragma unroll
    for (int s = 0; s < GM_NS - 1; s++) load_stage(s, s);

    for (int c = 0; c < nch; c++) {
        if (c + GM_NS - 1 < nch) {
            asm volatile("cp.async.wait_group %0;" :: "n"(GM_NS - 2) : "memory");
        } else {
            asm volatile("cp.async.wait_group 0;" ::: "memory");
        }
        __syncthreads();
        if (c + GM_NS - 1 < nch) load_stage((c + GM_NS - 1) % GM_NS, c + GM_NS - 1);

        const uint32_t st = sb + (c % GM_NS) * GM_STAGE;
#pragma unroll
        for (int ks = 0; ks < 2; ks++) {
            const int koff = ks * 32;
            uint32_t ah[2][4], al[2][4];
#pragma unroll
            for (int mf = 0; mf < 2; mf++) {
                uint32_t ra = st + (uint32_t)((mbase + mf * 16 + a_row) * GM_ROWB + koff + a_koff);
                ldsm4(ah[mf], ra);
                ldsm4(al[mf], ra + GM_TILE);
            }
            uint32_t bh[4][4], bl[4][4];
#pragma unroll
            for (int nf = 0; nf < 4; nf++) {
                uint32_t rb = st + 2 * GM_TILE +
                              (uint32_t)((nbase + nf * 16 + b_row) * GM_ROWB + koff + b_koff);
                ldsm4(bh[nf], rb);
                ldsm4(bl[nf], rb + GM_TILE);
            }
#pragma unroll
            for (int mf = 0; mf < 2; mf++)
#pragma unroll
                for (int nf = 0; nf < 4; nf++)
#pragma unroll
                    for (int h = 0; h < 2; h++) {
                        float* a4 = acc[mf][nf * 2 + h];
                        mma16816(a4, ah[mf], bh[nf][h * 2], bh[nf][h * 2 + 1]);
                        mma16816(a4, ah[mf], bl[nf][h * 2], bl[nf][h * 2 + 1]);
                        mma16816(a4, al[mf], bh[nf][h * 2], bh[nf][h * 2 + 1]);
                    }
        }
    }

    // epilogue
#pragma unroll
    for (int mf = 0; mf < 2; mf++)
#pragma unroll
        for (int nf = 0; nf < 8; nf++) {
            const int row0 = bm + mbase + mf * 16 + (lane >> 2);
            const int col = bn + nbase + nf * 8 + (lane & 3) * 2;
            const float* a4 = acc[mf][nf];
#pragma unroll
            for (int half = 0; half < 2; half++) {
                int row = row0 + half * 8;
                if (row >= M) continue;
                float v0 = a4[half * 2 + 0], v1 = a4[half * 2 + 1];
                if (outmap == 1) {
                    long crow = (long)row + row / TC + 1;
                    __nv_bfloat16 h0 = __float2bfloat16(v0);
                    __nv_bfloat16 h1 = __float2bfloat16(v1);
                    Chi[crow * DD + col] = h0;
                    Chi[crow * DD + col + 1] = h1;
                    Clo[crow * DD + col] = __float2bfloat16(v0 - __bfloat162float(h0));
                    Clo[crow * DD + col + 1] = __float2bfloat16(v1 - __bfloat162float(h1));
                } else if (outmap == 2) {
                    v0 *= oscale; v1 *= oscale;
                    __nv_bfloat16 h0 = __float2bfloat16(v0);
                    __nv_bfloat16 h1 = __float2bfloat16(v1);
                    Chi[(long)row * DD + col] = h0;
                    Chi[(long)row * DD + col + 1] = h1;
                    Clo[(long)row * DD + col] = __float2bfloat16(v0 - __bfloat162float(h0));
                    Clo[(long)row * DD + col + 1] = __float2bfloat16(v1 - __bfloat162float(h1));
                } else {
                    if (bias) { v0 += bias[col]; v1 += bias[col + 1]; }
                    *(float2*)(Cf + (long)row * DD + col) = make_float2(v0, v1);
                }
            }
        }
}

// ---------------- mma.sync flash attention, 3k<=q mask ----------------
// 128 queries/CTA (8 warps x 16 rows), 64-key tiles, cp.async double buffer.
#define FA_BQ 128
#define FA_BK 64
#define FA_ROWB 144
#define FA_TILE (64 * FA_ROWB)     // 9216
#define FA_STAGE (4 * FA_TILE)     // 36864 : Khi, Klo, Vhi, Vlo
#define FA_SMEM (2 * FA_STAGE)     // 73728

__global__ void __launch_bounds__(256)
attn_mma(const __nv_bfloat16* __restrict__ Qhi, const __nv_bfloat16* __restrict__ Qlo,
         const __nv_bfloat16* __restrict__ Khi, const __nv_bfloat16* __restrict__ Klo,
         const __nv_bfloat16* __restrict__ Vhi, const __nv_bfloat16* __restrict__ Vlo,
         __nv_bfloat16* __restrict__ Ohi, __nv_bfloat16* __restrict__ Olo)
{
    extern __shared__ char smem[];
    const uint32_t sb = smem_u32(smem);
    const int tid = threadIdx.x, wid = tid >> 5, lane = tid & 31;
    const int bh = blockIdx.y, b = bh >> 4, h = bh & 15;
    const int q0 = blockIdx.x * FA_BQ;

    const int grp = lane >> 3, rowg = lane & 7;
    const int a_row = (grp & 1) * 8 + rowg, a_koff = (grp >> 1) * 16;
    const int b_row = (grp >> 1) * 8 + rowg, b_koff = (grp & 1) * 16;
    const int v_row = (grp & 1) * 8 + rowg, v_koff = (grp >> 1) * 16;
    const int lq = lane >> 2, lc = (lane & 3) * 2;
    const int qrow0 = q0 + wid * 16 + lq;
    const int qrow1 = qrow0 + 8;

    // ---- stage Q (hi at 0, lo at +18432), extract fragments ----
#pragma unroll
    for (int it = 0; it < 8; it++) {
        int idx = it * 256 + tid;
        int t = idx >> 10, r = (idx >> 3) & 127, s = idx & 7;
        const __nv_bfloat16* src = t ? Qlo : Qhi;
        uint4 v = *(const uint4*)(src + (long)(b * TT + q0 + r) * DD + h * HD + s * 8);
        *(uint4*)(smem + t * 18432 + r * FA_ROWB + s * 16) = v;
    }
    __syncthreads();
    uint32_t qh[4][4], ql[4][4];
#pragma unroll
    for (int ks = 0; ks < 4; ks++) {
        uint32_t ra = sb + (uint32_t)((wid * 16 + a_row) * FA_ROWB + ks * 32 + a_koff);
        ldsm4(qh[ks], ra);
        ldsm4(ql[ks], ra + 18432);
    }
    __syncthreads();

    const int kmax = (q0 + FA_BQ - 1) / 3;
    const int nt = kmax / FA_BK + 1;

    auto load_kv = [&](int stg, int t) {
        const int kt = t * FA_BK;
        const uint32_t dst0 = sb + stg * FA_STAGE;
#pragma unroll
        for (int it = 0; it < 8; it++) {
            int idx = it * 256 + tid;
            int tt = idx >> 9, r = (idx >> 3) & 63, s = idx & 7;
            int kid = kt + r;
            if (kid > TKK - 1) kid = TKK - 1;
            const __nv_bfloat16* src = (tt == 0) ? Khi : (tt == 1) ? Klo : (tt == 2) ? Vhi : Vlo;
            const __nv_bfloat16* sp = src + (long)(b * TKK + kid) * DD + h * HD + s * 8;
            uint32_t dp = dst0 + (uint32_t)(tt * FA_TILE + r * FA_ROWB + s * 16);
            asm volatile("cp.async.cg.shared.global [%0], [%1], 16;" :: "r"(dp), "l"(sp));
        }
        asm volatile("cp.async.commit_group;" ::: "memory");
    };

    float Oa[8][4];
#pragma unroll
    for (int i = 0; i < 8; i++)
#pragma unroll
        for (int j = 0; j < 4; j++) Oa[i][j] = 0.f;
    float m0 = -1e30f, m1 = -1e30f, l0 = 0.f, l1 = 0.f;

    load_kv(0, 0);

    for (int t = 0; t < nt; t++) {
        const int stg = t & 1;
        if (t + 1 < nt) {
            load_kv(stg ^ 1, t + 1);
            asm volatile("cp.async.wait_group 1;" ::: "memory");
        } else {
            asm volatile("cp.async.wait_group 0;" ::: "memory");
        }
        __syncthreads();

        const int kt = t * FA_BK;
        const uint32_t stk = sb + stg * FA_STAGE;
        const uint32_t stv = stk + 2 * FA_TILE;

        // ---- S = Qs @ K^T (split) ----
        float S[8][4];
#pragma unroll
        for (int i = 0; i < 8; i++)
#pragma unroll
            for (int j = 0; j < 4; j++) S[i][j] = 0.f;

#pragma unroll
        for (int ng = 0; ng < 4; ng++) {
#pragma unroll
            for (int ks = 0; ks < 4; ks++) {
                uint32_t kh[4], kl[4];
                uint32_t rb = stk + (uint32_t)((ng * 16 + b_row) * FA_ROWB + ks * 32 + b_koff);
                ldsm4(kh, rb);
                ldsm4(kl, rb + FA_TILE);
                mma16816(S[2 * ng],     qh[ks], kh[0], kh[1]);
                mma16816(S[2 * ng + 1], qh[ks], kh[2], kh[3]);
                mma16816(S[2 * ng],     qh[ks], kl[0], kl[1]);
                mma16816(S[2 * ng + 1], qh[ks], kl[2], kl[3]);
                mma16816(S[2 * ng],     ql[ks], kh[0], kh[1]);
                mma16816(S[2 * ng + 1], ql[ks], kh[2], kh[3]);
            }
        }

        // ---- mask + online softmax ----
        float mx0 = -1e30f, mx1 = -1e30f;
#pragma unroll
        for (int nf = 0; nf < 8; nf++) {
            int key = kt + nf * 8 + lc;
            if (3 * key > qrow0)       S[nf][0] = -1e30f;
            if (3 * (key + 1) > qrow0) S[nf][1] = -1e30f;
            if (3 * key > qrow1)       S[nf][2] = -1e30f;
            if (3 * (key + 1) > qrow1) S[nf][3] = -1e30f;
            mx0 = fmaxf(mx0, fmaxf(S[nf][0], S[nf][1]));
            mx1 = fmaxf(mx1, fmaxf(S[nf][2], S[nf][3]));
        }
        mx0 = fmaxf(mx0, __shfl_xor_sync(0xFFFFFFFF, mx0, 1));
        mx0 = fmaxf(mx0, __shfl_xor_sync(0xFFFFFFFF, mx0, 2));
        mx1 = fmaxf(mx1, __shfl_xor_sync(0xFFFFFFFF, mx1, 1));
        mx1 = fmaxf(mx1, __shfl_xor_sync(0xFFFFFFFF, mx1, 2));
        float mn0 = fmaxf(m0, mx0), mn1 = fmaxf(m1, mx1);
        float c0 = __expf(m0 - mn0), c1 = __expf(m1 - mn1);

        float ls0 = 0.f, ls1 = 0.f;
#pragma unroll
        for (int nf = 0; nf < 8; nf++) {
            S[nf][0] = __expf(S[nf][0] - mn0);
            S[nf][1] = __expf(S[nf][1] - mn0);
            S[nf][2] = __expf(S[nf][2] - mn1);
            S[nf][3] = __expf(S[nf][3] - mn1);
            ls0 += S[nf][0] + S[nf][1];
            ls1 += S[nf][2] + S[nf][3];
        }
        ls0 += __shfl_xor_sync(0xFFFFFFFF, ls0, 1);
        ls0 += __shfl_xor_sync(0xFFFFFFFF, ls0, 2);
        ls1 += __shfl_xor_sync(0xFFFFFFFF, ls1, 1);
        ls1 += __shfl_xor_sync(0xFFFFFFFF, ls1, 2);
        l0 = l0 * c0 + ls0;
        l1 = l1 * c1 + ls1;
        m0 = mn0; m1 = mn1;

#pragma unroll
        for (int nf = 0; nf < 8; nf++) {
            Oa[nf][0] *= c0; Oa[nf][1] *= c0;
            Oa[nf][2] *= c1; Oa[nf][3] *= c1;
        }

        // ---- O += P @ V (P split hi/lo, V split hi/lo) ----
#pragma unroll
        for (int g = 0; g < 4; g++) {
            uint32_t ph[4], pl[4];
            float p00 = S[2 * g][0], p01 = S[2 * g][1], p02 = S[2 * g][2], p03 = S[2 * g][3];
            float p10 = S[2 * g + 1][0], p11 = S[2 * g + 1][1], p12 = S[2 * g + 1][2], p13 = S[2 * g + 1][3];
            ph[0] = packbf2(p00, p01); ph[1] = packbf2(p02, p03);
            ph[2] = packbf2(p10, p11); ph[3] = packbf2(p12, p13);
            float r00 = p00 - __bfloat162float(__float2bfloat16(p00));
            float r01 = p01 - __bfloat162float(__float2bfloat16(p01));
            float r02 = p02 - __bfloat162float(__float2bfloat16(p02));
            float r03 = p03 - __bfloat162float(__float2bfloat16(p03));
            float r10 = p10 - __bfloat162float(__float2bfloat16(p10));
            float r11 = p11 - __bfloat162float(__float2bfloat16(p11));
            float r12 = p12 - __bfloat162float(__float2bfloat16(p12));
            float r13 = p13 - __bfloat162float(__float2bfloat16(p13));
            pl[0] = packbf2(r00, r01); pl[1] = packbf2(r02, r03);
            pl[2] = packbf2(r10, r11); pl[3] = packbf2(r12, r13);
#pragma unroll
            for (int dg = 0; dg < 4; dg++) {
                uint32_t vh[4], vl[4];
                uint32_t rv = stv + (uint32_t)((g * 16 + v_row) * FA_ROWB + dg * 32 + v_koff);
                ldsm4t(vh, rv);
                ldsm4t(vl, rv + FA_TILE);
                mma16816(Oa[2 * dg],     ph, vh[0], vh[1]);
                mma16816(Oa[2 * dg + 1], ph, vh[2], vh[3]);
                mma16816(Oa[2 * dg],     ph, vl[0], vl[1]);
                mma16816(Oa[2 * dg + 1], ph, vl[2], vl[3]);
                mma16816(Oa[2 * dg],     pl, vh[0], vh[1]);
                mma16816(Oa[2 * dg + 1], pl, vh[2], vh[3]);
            }
        }
        __syncthreads();
    }

    // ---- normalize + store bf16 hi/lo ----
    const float inv0 = 1.f / l0, inv1 = 1.f / l1;
#pragma unroll
    for (int nf = 0; nf < 8; nf++) {
#pragma unroll
        for (int r = 0; r < 2; r++) {
            int row = (r == 0) ? qrow0 : qrow1;
            float inv = (r == 0) ? inv0 : inv1;
            float v0 = Oa[nf][r * 2 + 0] * inv;
            float v1 = Oa[nf][r * 2 + 1] * inv;
            long base = (long)(b * TT + row) * DD + h * HD + nf * 8 + lc;
            __nv_bfloat16 h0 = __float2bfloat16(v0);
            __nv_bfloat16 h1 = __float2bfloat16(v1);
            *(uint32_t*)(Ohi + base) =
                (uint32_t)__bfloat16_as_ushort(h0) | ((uint32_t)__bfloat16_as_ushort(h1) << 16);
            __nv_bfloat16 e0 = __float2bfloat16(v0 - __bfloat162float(h0));
            __nv_bfloat16 e1 = __float2bfloat16(v1 - __bfloat162float(h1));
            *(uint32_t*)(Olo + base) =
                (uint32_t)__bfloat16_as_ushort(e0) | ((uint32_t)__bfloat16_as_ushort(e1) << 16);
        }
    }
}

// ---------------- launch ----------------
extern "C" void kernel_launch(void* const* d_in, const int* in_sizes, int n_in,
                              void* d_out, int out_size)
{
    const float* x     = (const float*)d_in[0];
    const float* Wq    = (const float*)d_in[1];
    const float* Wk    = (const float*)d_in[2];
    const float* Wv    = (const float*)d_in[3];
    const float* Wo    = (const float*)d_in[4];
    const float* bo    = (const float*)d_in[5];
    const float* Wconv = (const float*)d_in[6];
    float* out = (float*)d_out;

    __nv_bfloat16 *xhi, *xlo, *wqh, *wql, *wkh, *wkl, *wvh, *wvl, *woh, *wol, *wch, *wcl;
    __nv_bfloat16 *khi, *klo, *qhi, *qlo, *kbh, *kbl, *vbh, *vbl, *ohi, *olo;
    cudaGetSymbolAddress((void**)&xhi, g_xhi);  cudaGetSymbolAddress((void**)&xlo, g_xlo);
    cudaGetSymbolAddress((void**)&wqh, g_wqhi); cudaGetSymbolAddress((void**)&wql, g_wqlo);
    cudaGetSymbolAddress((void**)&wkh, g_wkhi); cudaGetSymbolAddress((void**)&wkl, g_wklo);
    cudaGetSymbolAddress((void**)&wvh, g_wvhi); cudaGetSymbolAddress((void**)&wvl, g_wvlo);
    cudaGetSymbolAddress((void**)&woh, g_wohi); cudaGetSymbolAddress((void**)&wol, g_wolo);
    cudaGetSymbolAddress((void**)&wch, g_wchi); cudaGetSymbolAddress((void**)&wcl, g_wclo);
    cudaGetSymbolAddress((void**)&khi, g_khi2); cudaGetSymbolAddress((void**)&klo, g_klo2);
    cudaGetSymbolAddress((void**)&qhi, g_qhi);  cudaGetSymbolAddress((void**)&qlo, g_qlo);
    cudaGetSymbolAddress((void**)&kbh, g_kbhi); cudaGetSymbolAddress((void**)&kbl, g_kblo);
    cudaGetSymbolAddress((void**)&vbh, g_vbhi); cudaGetSymbolAddress((void**)&vbl, g_vblo);
    cudaGetSymbolAddress((void**)&ohi, g_ohi);  cudaGetSymbolAddress((void**)&olo, g_olo);

    cudaFuncSetAttribute(gemm_mma, cudaFuncAttributeMaxDynamicSharedMemorySize, GM_SMEM);
    cudaFuncSetAttribute(attn_mma, cudaFuncAttributeMaxDynamicSharedMemorySize, FA_SMEM);

    // conversions
    { int n = BB * TT * DD; split_kernel<<<(n + 255) / 256, 256>>>(x, xhi, xlo, n); }
    { int n = 4 * DD * DD;
      split4_kernel<<<n / 256, 256>>>(Wq, Wk, Wv, Wo,
                                      wqh, wql, wkh, wkl, wvh, wvl, woh, wol); }
    { int n = DD * DD * 3; repack_conv_kernel<<<(n + 255) / 256, 256>>>(Wconv, wch, wcl); }
    { int n = BB * DD; copy_row0_kernel<<<(n + 255) / 256, 256>>>(x, khi, klo); }

    // conv GEMM -> k_tmp (scatter, bf16 hi/lo out)
    {
        dim3 grid(DD / GM_BN, (BB * TC + GM_BM - 1) / GM_BM, 1);
        gemm_mma<<<grid, 256, GM_SMEM>>>(xhi, xlo, 3L * DD, wch, wcl, nullptr, nullptr, nullptr,
                                         nullptr, khi, klo, nullptr, nullptr,
                                         BB * TC, 3 * DD, 1, 1.f);
    }
    // Q = (x @ Wq^T) * 0.125 -> bf16 hi/lo
    {
        dim3 grid(DD / GM_BN, (BB * TT + GM_BM - 1) / GM_BM, 1);
        gemm_mma<<<grid, 256, GM_SMEM>>>(xhi, xlo, (long)DD, wqh, wql, nullptr, nullptr, nullptr,
                                         nullptr, qhi, qlo, nullptr, nullptr,
                                         BB * TT, DD, 2, 0.125f);
    }
    // K, V = k_tmp @ Wk^T / Wv^T -> bf16 hi/lo (fused launch, z picks weight)
    {
        dim3 grid(DD / GM_BN, (BB * TKK + GM_BM - 1) / GM_BM, 2);
        gemm_mma<<<grid, 256, GM_SMEM>>>(khi, klo, (long)DD, wkh, wkl, wvh, wvl, nullptr,
                                         nullptr, kbh, kbl, vbh, vbl,
                                         BB * TKK, DD, 2, 1.f);
    }
    // attention (tensor-core)
    {
        dim3 grid(TT / FA_BQ, BB * HH);                        // (24, 64)
        attn_mma<<<grid, 256, FA_SMEM>>>(qhi, qlo, kbh, kbl, vbh, vbl, ohi, olo);
    }
    // out = o @ Wo^T + bo
    {
        dim3 grid(DD / GM_BN, (BB * TT + GM_BM - 1) / GM_BM, 1);
        gemm_mma<<<grid, 256, GM_SMEM>>>(ohi, olo, (long)DD, woh, wol, nullptr, nullptr, bo,
                                         out, nullptr, nullptr, nullptr, nullptr,
                                         BB * TT, DD, 0, 1.f);
    }
}

// round 11
// speedup vs baseline: 1.0059x; 1.0059x over previous
#include <cuda_runtime.h>
#include <cuda_bf16.h>
#include <cstdint>
#include <math.h>

// Problem dims
#define BB 4
#define TT 3072
#define DD 1024
#define HH 16
#define HD 64
#define TC 1024          // conv outputs per batch
#define TKK 1025         // k_tmp rows per batch

// ---------------- static scratch ----------------
__device__ __nv_bfloat16 g_xhi[BB * TT * DD], g_xlo[BB * TT * DD];
__device__ __nv_bfloat16 g_wqhi[DD * DD], g_wqlo[DD * DD];
__device__ __nv_bfloat16 g_wkhi[DD * DD], g_wklo[DD * DD];
__device__ __nv_bfloat16 g_wvhi[DD * DD], g_wvlo[DD * DD];
__device__ __nv_bfloat16 g_wohi[DD * DD], g_wolo[DD * DD];
__device__ __nv_bfloat16 g_wchi[DD * 3 * DD], g_wclo[DD * 3 * DD];
__device__ __nv_bfloat16 g_khi2[BB * TKK * DD], g_klo2[BB * TKK * DD];  // k_tmp hi/lo
__device__ __nv_bfloat16 g_qhi[BB * TT * DD], g_qlo[BB * TT * DD];      // Q (pre-scaled)
__device__ __nv_bfloat16 g_kbhi[BB * TKK * DD], g_kblo[BB * TKK * DD];  // K proj
__device__ __nv_bfloat16 g_vbhi[BB * TKK * DD], g_vblo[BB * TKK * DD];  // V proj
__device__ __nv_bfloat16 g_ohi[BB * TT * DD], g_olo[BB * TT * DD];      // attn out

// ---------------- helpers ----------------
__device__ __forceinline__ uint32_t smem_u32(const void* p) {
    uint32_t a;
    asm("{ .reg .u64 t; cvta.to.shared.u64 t, %1; cvt.u32.u64 %0, t; }" : "=r"(a) : "l"(p));
    return a;
}
__device__ __forceinline__ void ldsm4(uint32_t* r, uint32_t addr) {
    asm volatile("ldmatrix.sync.aligned.m8n8.x4.shared.b16 {%0,%1,%2,%3}, [%4];"
        : "=r"(r[0]), "=r"(r[1]), "=r"(r[2]), "=r"(r[3]) : "r"(addr));
}
__device__ __forceinline__ void ldsm4t(uint32_t* r, uint32_t addr) {
    asm volatile("ldmatrix.sync.aligned.m8n8.x4.trans.shared.b16 {%0,%1,%2,%3}, [%4];"
        : "=r"(r[0]), "=r"(r[1]), "=r"(r[2]), "=r"(r[3]) : "r"(addr));
}
__device__ __forceinline__ void mma16816(float* c, const uint32_t* a, uint32_t b0, uint32_t b1) {
    asm volatile("mma.sync.aligned.m16n8k16.row.col.f32.bf16.bf16.f32 "
        "{%0,%1,%2,%3}, {%4,%5,%6,%7}, {%8,%9}, {%0,%1,%2,%3};"
        : "+f"(c[0]), "+f"(c[1]), "+f"(c[2]), "+f"(c[3])
        : "r"(a[0]), "r"(a[1]), "r"(a[2]), "r"(a[3]), "r"(b0), "r"(b1));
}
__device__ __forceinline__ uint32_t packbf2(float x, float y) {
    uint32_t lo = __bfloat16_as_ushort(__float2bfloat16(x));
    uint32_t hi = __bfloat16_as_ushort(__float2bfloat16(y));
    return lo | (hi << 16);
}

// ---------------- split / repack kernels ----------------
__global__ void split_kernel(const float* __restrict__ s, __nv_bfloat16* __restrict__ hi,
                             __nv_bfloat16* __restrict__ lo, int n) {
    int i = blockIdx.x * 256 + threadIdx.x;
    if (i >= n) return;
    float v = s[i];
    __nv_bfloat16 h = __float2bfloat16(v);
    hi[i] = h;
    lo[i] = __float2bfloat16(v - __bfloat162float(h));
}
// 4 weight matrices (each DD*DD = 1<<20 elems) in one launch
__global__ void split4_kernel(const float* __restrict__ w0, const float* __restrict__ w1,
                              const float* __restrict__ w2, const float* __restrict__ w3,
                              __nv_bfloat16* __restrict__ h0, __nv_bfloat16* __restrict__ l0,
                              __nv_bfloat16* __restrict__ h1, __nv_bfloat16* __restrict__ l1,
                              __nv_bfloat16* __restrict__ h2, __nv_bfloat16* __restrict__ l2,
                              __nv_bfloat16* __restrict__ h3, __nv_bfloat16* __restrict__ l3) {
    int i = blockIdx.x * 256 + threadIdx.x;
    int w = i >> 20, j = i & ((1 << 20) - 1);
    const float* s = (w == 0) ? w0 : (w == 1) ? w1 : (w == 2) ? w2 : w3;
    __nv_bfloat16* hp = (w == 0) ? h0 : (w == 1) ? h1 : (w == 2) ? h2 : h3;
    __nv_bfloat16* lp = (w == 0) ? l0 : (w == 1) ? l1 : (w == 2) ? l2 : l3;
    float v = s[j];
    __nv_bfloat16 h = __float2bfloat16(v);
    hp[j] = h;
    lp[j] = __float2bfloat16(v - __bfloat162float(h));
}
__global__ void repack_conv_kernel(const float* __restrict__ W, __nv_bfloat16* __restrict__ hi,
                                   __nv_bfloat16* __restrict__ lo) {
    int idx = blockIdx.x * 256 + threadIdx.x;
    if (idx >= DD * DD * 3) return;
    int o = idx / (DD * 3);
    int r = idx % (DD * 3);
    int i = r / 3, kw = r % 3;
    float v = W[idx];
    __nv_bfloat16 h = __float2bfloat16(v);
    long d = (long)o * (3 * DD) + kw * DD + i;
    hi[d] = h;
    lo[d] = __float2bfloat16(v - __bfloat162float(h));
}
__global__ void copy_row0_kernel(const float* __restrict__ x, __nv_bfloat16* __restrict__ khi,
                                 __nv_bfloat16* __restrict__ klo) {
    int idx = blockIdx.x * 256 + threadIdx.x;
    if (idx >= BB * DD) return;
    int b = idx / DD, i = idx % DD;
    float v = x[(long)b * TT * DD + i];
    __nv_bfloat16 h = __float2bfloat16(v);
    long d = (long)b * TKK * DD + i;
    khi[d] = h;
    klo[d] = __float2bfloat16(v - __bfloat162float(h));
}

// ---------------- mma.sync GEMM: C[M,1024] = A @ B^T (bf16x3 split) ----------------
// cp.async double-buffered (2 stages, 80KB -> 2 CTAs/SM).
// outmap 0: fp32 Cf (+bias).  outmap 1: conv scatter -> bf16 hi/lo.  outmap 2: bf16 hi/lo (scaled).
// blockIdx.z==1 selects the secondary B/C pointers (fused K/V launch).
#define GM_BM 128
#define GM_BN 128
#define GM_BK 32
#define GM_ROWB 80
#define GM_TILE (128 * GM_ROWB)        // 10240
#define GM_STAGE (4 * GM_TILE)         // 40960
#define GM_SMEM (2 * GM_STAGE)         // 81920

__global__ void __launch_bounds__(256)
gemm_mma(const __nv_bfloat16* Ahi, const __nv_bfloat16* Alo, long lda,
         const __nv_bfloat16* Bhi, const __nv_bfloat16* Blo,
         const __nv_bfloat16* Bhi2, const __nv_bfloat16* Blo2,
         const float* bias,
         float* Cf, __nv_bfloat16* Chi, __nv_bfloat16* Clo,
         __nv_bfloat16* Chi2, __nv_bfloat16* Clo2,
         int M, int K, int outmap, float oscale)
{
    if (blockIdx.z == 1) { Bhi = Bhi2; Blo = Blo2; Chi = Chi2; Clo = Clo2; }
    extern __shared__ char smem[];
    const uint32_t sb = smem_u32(smem);
    const int tid = threadIdx.x;
    const int wid = tid >> 5, lane = tid & 31;
    const int bm = blockIdx.y * GM_BM, bn = blockIdx.x * GM_BN;
    const int mbase = (wid & 3) * 32;
    const int nbase = (wid >> 2) * 64;

    const int grp = lane >> 3, rowg = lane & 7;
    const int a_row = (grp & 1) * 8 + rowg;
    const int a_koff = (grp >> 1) * 16;
    const int b_row = (grp >> 1) * 8 + rowg;
    const int b_koff = (grp & 1) * 16;

    float acc[2][8][4];
#pragma unroll
    for (int i = 0; i < 2; i++)
#pragma unroll
        for (int j = 0; j < 8; j++)
#pragma unroll
            for (int k = 0; k < 4; k++) acc[i][j][k] = 0.f;

    auto load_stage = [&](int stg, int c) {
        const uint32_t base = sb + stg * GM_STAGE;
        const int k0 = c * GM_BK;
#pragma unroll
        for (int it = 0; it < 8; it++) {
            int i = it * 256 + tid;
            int t = i >> 9;               // 0 Ahi, 1 Alo, 2 Bhi, 3 Blo
            int r = (i >> 2) & 127;
            int s = i & 3;
            const __nv_bfloat16* sp;
            int sz = 16;
            if (t < 2) {
                int row = bm + r;
                if (row >= M) { row = bm; sz = 0; }
                sp = (t ? Alo : Ahi) + (long)row * lda + k0 + s * 8;
            } else {
                sp = ((t == 3) ? Blo : Bhi) + (long)(bn + r) * K + k0 + s * 8;
            }
            uint32_t dp = base + (uint32_t)(t * GM_TILE + r * GM_ROWB + s * 16);
            asm volatile("cp.async.cg.shared.global [%0], [%1], 16, %2;"
                         :: "r"(dp), "l"(sp), "r"(sz));
        }
        asm volatile("cp.async.commit_group;" ::: "memory");
    };

    const int nch = K / GM_BK;
    load_stage(0, 0);

    for (int c = 0; c < nch; c++) {
        asm volatile("cp.async.wait_group 0;" ::: "memory");
        __syncthreads();
        if (c + 1 < nch) load_stage((c + 1) & 1, c + 1);

        const uint32_t st = sb + (c & 1) * GM_STAGE;
#pragma unroll
        for (int ks = 0; ks < 2; ks++) {
            const int koff = ks * 32;
            uint32_t ah[2][4], al[2][4];
#pragma unroll
            for (int mf = 0; mf < 2; mf++) {
                uint32_t ra = st + (uint32_t)((mbase + mf * 16 + a_row) * GM_ROWB + koff + a_koff);
                ldsm4(ah[mf], ra);
                ldsm4(al[mf], ra + GM_TILE);
            }
            uint32_t bh[4][4], bl[4][4];
#pragma unroll
            for (int nf = 0; nf < 4; nf++) {
                uint32_t rb = st + 2 * GM_TILE +
                              (uint32_t)((nbase + nf * 16 + b_row) * GM_ROWB + koff + b_koff);
                ldsm4(bh[nf], rb);
                ldsm4(bl[nf], rb + GM_TILE);
            }
#pragma unroll
            for (int mf = 0; mf < 2; mf++)
#pragma unroll
                for (int nf = 0; nf < 4; nf++)
#pragma unroll
                    for (int h = 0; h < 2; h++) {
                        float* a4 = acc[mf][nf * 2 + h];
                        mma16816(a4, ah[mf], bh[nf][h * 2], bh[nf][h * 2 + 1]);
                        mma16816(a4, ah[mf], bl[nf][h * 2], bl[nf][h * 2 + 1]);
                        mma16816(a4, al[mf], bh[nf][h * 2], bh[nf][h * 2 + 1]);
                    }
        }
    }

    // epilogue
#pragma unroll
    for (int mf = 0; mf < 2; mf++)
#pragma unroll
        for (int nf = 0; nf < 8; nf++) {
            const int row0 = bm + mbase + mf * 16 + (lane >> 2);
            const int col = bn + nbase + nf * 8 + (lane & 3) * 2;
            const float* a4 = acc[mf][nf];
#pragma unroll
            for (int half = 0; half < 2; half++) {
                int row = row0 + half * 8;
                if (row >= M) continue;
                float v0 = a4[half * 2 + 0], v1 = a4[half * 2 + 1];
                if (outmap == 1) {
                    long crow = (long)row + row / TC + 1;
                    __nv_bfloat16 h0 = __float2bfloat16(v0);
                    __nv_bfloat16 h1 = __float2bfloat16(v1);
                    Chi[crow * DD + col] = h0;
                    Chi[crow * DD + col + 1] = h1;
                    Clo[crow * DD + col] = __float2bfloat16(v0 - __bfloat162float(h0));
                    Clo[crow * DD + col + 1] = __float2bfloat16(v1 - __bfloat162float(h1));
                } else if (outmap == 2) {
                    v0 *= oscale; v1 *= oscale;
                    __nv_bfloat16 h0 = __float2bfloat16(v0);
                    __nv_bfloat16 h1 = __float2bfloat16(v1);
                    Chi[(long)row * DD + col] = h0;
                    Chi[(long)row * DD + col + 1] = h1;
                    Clo[(long)row * DD + col] = __float2bfloat16(v0 - __bfloat162float(h0));
                    Clo[(long)row * DD + col + 1] = __float2bfloat16(v1 - __bfloat162float(h1));
                } else {
                    if (bias) { v0 += bias[col]; v1 += bias[col + 1]; }
                    *(float2*)(Cf + (long)row * DD + col) = make_float2(v0, v1);
                }
            }
        }
}

// ---------------- mma.sync flash attention, 3k<=q mask ----------------
// 128 queries/CTA (8 warps x 16 rows), 64-key tiles, cp.async double buffer.
#define FA_BQ 128
#define FA_BK 64
#define FA_ROWB 144
#define FA_TILE (64 * FA_ROWB)     // 9216
#define FA_STAGE (4 * FA_TILE)     // 36864 : Khi, Klo, Vhi, Vlo
#define FA_SMEM (2 * FA_STAGE)     // 73728

__global__ void __launch_bounds__(256)
attn_mma(const __nv_bfloat16* __restrict__ Qhi, const __nv_bfloat16* __restrict__ Qlo,
         const __nv_bfloat16* __restrict__ Khi, const __nv_bfloat16* __restrict__ Klo,
         const __nv_bfloat16* __restrict__ Vhi, const __nv_bfloat16* __restrict__ Vlo,
         __nv_bfloat16* __restrict__ Ohi, __nv_bfloat16* __restrict__ Olo)
{
    extern __shared__ char smem[];
    const uint32_t sb = smem_u32(smem);
    const int tid = threadIdx.x, wid = tid >> 5, lane = tid & 31;
    const int bh = blockIdx.y, b = bh >> 4, h = bh & 15;
    const int q0 = blockIdx.x * FA_BQ;

    const int grp = lane >> 3, rowg = lane & 7;
    const int a_row = (grp & 1) * 8 + rowg, a_koff = (grp >> 1) * 16;
    const int b_row = (grp >> 1) * 8 + rowg, b_koff = (grp & 1) * 16;
    const int v_row = (grp & 1) * 8 + rowg, v_koff = (grp >> 1) * 16;
    const int lq = lane >> 2, lc = (lane & 3) * 2;
    const int qrow0 = q0 + wid * 16 + lq;
    const int qrow1 = qrow0 + 8;

    // ---- stage Q (hi at 0, lo at +18432), extract fragments ----
#pragma unroll
    for (int it = 0; it < 8; it++) {
        int idx = it * 256 + tid;
        int t = idx >> 10, r = (idx >> 3) & 127, s = idx & 7;
        const __nv_bfloat16* src = t ? Qlo : Qhi;
        uint4 v = *(const uint4*)(src + (long)(b * TT + q0 + r) * DD + h * HD + s * 8);
        *(uint4*)(smem + t * 18432 + r * FA_ROWB + s * 16) = v;
    }
    __syncthreads();
    uint32_t qh[4][4], ql[4][4];
#pragma unroll
    for (int ks = 0; ks < 4; ks++) {
        uint32_t ra = sb + (uint32_t)((wid * 16 + a_row) * FA_ROWB + ks * 32 + a_koff);
        ldsm4(qh[ks], ra);
        ldsm4(ql[ks], ra + 18432);
    }
    __syncthreads();

    const int kmax = (q0 + FA_BQ - 1) / 3;
    const int nt = kmax / FA_BK + 1;

    auto load_kv = [&](int stg, int t) {
        const int kt = t * FA_BK;
        const uint32_t dst0 = sb + stg * FA_STAGE;
#pragma unroll
        for (int it = 0; it < 8; it++) {
            int idx = it * 256 + tid;
            int tt = idx >> 9, r = (idx >> 3) & 63, s = idx & 7;
            int kid = kt + r;
            if (kid > TKK - 1) kid = TKK - 1;
            const __nv_bfloat16* src = (tt == 0) ? Khi : (tt == 1) ? Klo : (tt == 2) ? Vhi : Vlo;
            const __nv_bfloat16* sp = src + (long)(b * TKK + kid) * DD + h * HD + s * 8;
            uint32_t dp = dst0 + (uint32_t)(tt * FA_TILE + r * FA_ROWB + s * 16);
            asm volatile("cp.async.cg.shared.global [%0], [%1], 16;" :: "r"(dp), "l"(sp));
        }
        asm volatile("cp.async.commit_group;" ::: "memory");
    };

    float Oa[8][4];
#pragma unroll
    for (int i = 0; i < 8; i++)
#pragma unroll
        for (int j = 0; j < 4; j++) Oa[i][j] = 0.f;
    float m0 = -1e30f, m1 = -1e30f, l0 = 0.f, l1 = 0.f;

    load_kv(0, 0);

    for (int t = 0; t < nt; t++) {
        const int stg = t & 1;
        if (t + 1 < nt) {
            load_kv(stg ^ 1, t + 1);
            asm volatile("cp.async.wait_group 1;" ::: "memory");
        } else {
            asm volatile("cp.async.wait_group 0;" ::: "memory");
        }
        __syncthreads();

        const int kt = t * FA_BK;
        const uint32_t stk = sb + stg * FA_STAGE;
        const uint32_t stv = stk + 2 * FA_TILE;

        // ---- S = Qs @ K^T (split) ----
        float S[8][4];
#pragma unroll
        for (int i = 0; i < 8; i++)
#pragma unroll
            for (int j = 0; j < 4; j++) S[i][j] = 0.f;

#pragma unroll
        for (int ng = 0; ng < 4; ng++) {
#pragma unroll
            for (int ks = 0; ks < 4; ks++) {
                uint32_t kh[4], kl[4];
                uint32_t rb = stk + (uint32_t)((ng * 16 + b_row) * FA_ROWB + ks * 32 + b_koff);
                ldsm4(kh, rb);
                ldsm4(kl, rb + FA_TILE);
                mma16816(S[2 * ng],     qh[ks], kh[0], kh[1]);
                mma16816(S[2 * ng + 1], qh[ks], kh[2], kh[3]);
                mma16816(S[2 * ng],     qh[ks], kl[0], kl[1]);
                mma16816(S[2 * ng + 1], qh[ks], kl[2], kl[3]);
                mma16816(S[2 * ng],     ql[ks], kh[0], kh[1]);
                mma16816(S[2 * ng + 1], ql[ks], kh[2], kh[3]);
            }
        }

        // ---- mask + online softmax ----
        float mx0 = -1e30f, mx1 = -1e30f;
#pragma unroll
        for (int nf = 0; nf < 8; nf++) {
            int key = kt + nf * 8 + lc;
            if (3 * key > qrow0)       S[nf][0] = -1e30f;
            if (3 * (key + 1) > qrow0) S[nf][1] = -1e30f;
            if (3 * key > qrow1)       S[nf][2] = -1e30f;
            if (3 * (key + 1) > qrow1) S[nf][3] = -1e30f;
            mx0 = fmaxf(mx0, fmaxf(S[nf][0], S[nf][1]));
            mx1 = fmaxf(mx1, fmaxf(S[nf][2], S[nf][3]));
        }
        mx0 = fmaxf(mx0, __shfl_xor_sync(0xFFFFFFFF, mx0, 1));
        mx0 = fmaxf(mx0, __shfl_xor_sync(0xFFFFFFFF, mx0, 2));
        mx1 = fmaxf(mx1, __shfl_xor_sync(0xFFFFFFFF, mx1, 1));
        mx1 = fmaxf(mx1, __shfl_xor_sync(0xFFFFFFFF, mx1, 2));
        float mn0 = fmaxf(m0, mx0), mn1 = fmaxf(m1, mx1);
        float c0 = __expf(m0 - mn0), c1 = __expf(m1 - mn1);

        float ls0 = 0.f, ls1 = 0.f;
#pragma unroll
        for (int nf = 0; nf < 8; nf++) {
            S[nf][0] = __expf(S[nf][0] - mn0);
            S[nf][1] = __expf(S[nf][1] - mn0);
            S[nf][2] = __expf(S[nf][2] - mn1);
            S[nf][3] = __expf(S[nf][3] - mn1);
            ls0 += S[nf][0] + S[nf][1];
            ls1 += S[nf][2] + S[nf][3];
        }
        ls0 += __shfl_xor_sync(0xFFFFFFFF, ls0, 1);
        ls0 += __shfl_xor_sync(0xFFFFFFFF, ls0, 2);
        ls1 += __shfl_xor_sync(0xFFFFFFFF, ls1, 1);
        ls1 += __shfl_xor_sync(0xFFFFFFFF, ls1, 2);
        l0 = l0 * c0 + ls0;
        l1 = l1 * c1 + ls1;
        m0 = mn0; m1 = mn1;

#pragma unroll
        for (int nf = 0; nf < 8; nf++) {
            Oa[nf][0] *= c0; Oa[nf][1] *= c0;
            Oa[nf][2] *= c1; Oa[nf][3] *= c1;
        }

        // ---- O += P @ V (P split hi/lo, V split hi/lo) ----
#pragma unroll
        for (int g = 0; g < 4; g++) {
            uint32_t ph[4], pl[4];
            float p00 = S[2 * g][0], p01 = S[2 * g][1], p02 = S[2 * g][2], p03 = S[2 * g][3];
            float p10 = S[2 * g + 1][0], p11 = S[2 * g + 1][1], p12 = S[2 * g + 1][2], p13 = S[2 * g + 1][3];
            ph[0] = packbf2(p00, p01); ph[1] = packbf2(p02, p03);
            ph[2] = packbf2(p10, p11); ph[3] = packbf2(p12, p13);
            float r00 = p00 - __bfloat162float(__float2bfloat16(p00));
            float r01 = p01 - __bfloat162float(__float2bfloat16(p01));
            float r02 = p02 - __bfloat162float(__float2bfloat16(p02));
            float r03 = p03 - __bfloat162float(__float2bfloat16(p03));
            float r10 = p10 - __bfloat162float(__float2bfloat16(p10));
            float r11 = p11 - __bfloat162float(__float2bfloat16(p11));
            float r12 = p12 - __bfloat162float(__float2bfloat16(p12));
            float r13 = p13 - __bfloat162float(__float2bfloat16(p13));
            pl[0] = packbf2(r00, r01); pl[1] = packbf2(r02, r03);
            pl[2] = packbf2(r10, r11); pl[3] = packbf2(r12, r13);
#pragma unroll
            for (int dg = 0; dg < 4; dg++) {
                uint32_t vh[4], vl[4];
                uint32_t rv = stv + (uint32_t)((g * 16 + v_row) * FA_ROWB + dg * 32 + v_koff);
                ldsm4t(vh, rv);
                ldsm4t(vl, rv + FA_TILE);
                mma16816(Oa[2 * dg],     ph, vh[0], vh[1]);
                mma16816(Oa[2 * dg + 1], ph, vh[2], vh[3]);
                mma16816(Oa[2 * dg],     ph, vl[0], vl[1]);
                mma16816(Oa[2 * dg + 1], ph, vl[2], vl[3]);
                mma16816(Oa[2 * dg],     pl, vh[0], vh[1]);
                mma16816(Oa[2 * dg + 1], pl, vh[2], vh[3]);
            }
        }
        __syncthreads();
    }

    // ---- normalize + store bf16 hi/lo ----
    const float inv0 = 1.f / l0, inv1 = 1.f / l1;
#pragma unroll
    for (int nf = 0; nf < 8; nf++) {
#pragma unroll
        for (int r = 0; r < 2; r++) {
            int row = (r == 0) ? qrow0 : qrow1;
            float inv = (r == 0) ? inv0 : inv1;
            float v0 = Oa[nf][r * 2 + 0] * inv;
            float v1 = Oa[nf][r * 2 + 1] * inv;
            long base = (long)(b * TT + row) * DD + h * HD + nf * 8 + lc;
            __nv_bfloat16 h0 = __float2bfloat16(v0);
            __nv_bfloat16 h1 = __float2bfloat16(v1);
            *(uint32_t*)(Ohi + base) =
                (uint32_t)__bfloat16_as_ushort(h0) | ((uint32_t)__bfloat16_as_ushort(h1) << 16);
            __nv_bfloat16 e0 = __float2bfloat16(v0 - __bfloat162float(h0));
            __nv_bfloat16 e1 = __float2bfloat16(v1 - __bfloat162float(h1));
            *(uint32_t*)(Olo + base) =
                (uint32_t)__bfloat16_as_ushort(e0) | ((uint32_t)__bfloat16_as_ushort(e1) << 16);
        }
    }
}

// ---------------- launch ----------------
extern "C" void kernel_launch(void* const* d_in, const int* in_sizes, int n_in,
                              void* d_out, int out_size)
{
    const float* x     = (const float*)d_in[0];
    const float* Wq    = (const float*)d_in[1];
    const float* Wk    = (const float*)d_in[2];
    const float* Wv    = (const float*)d_in[3];
    const float* Wo    = (const float*)d_in[4];
    const float* bo    = (const float*)d_in[5];
    const float* Wconv = (const float*)d_in[6];
    float* out = (float*)d_out;

    __nv_bfloat16 *xhi, *xlo, *wqh, *wql, *wkh, *wkl, *wvh, *wvl, *woh, *wol, *wch, *wcl;
    __nv_bfloat16 *khi, *klo, *qhi, *qlo, *kbh, *kbl, *vbh, *vbl, *ohi, *olo;
    cudaGetSymbolAddress((void**)&xhi, g_xhi);  cudaGetSymbolAddress((void**)&xlo, g_xlo);
    cudaGetSymbolAddress((void**)&wqh, g_wqhi); cudaGetSymbolAddress((void**)&wql, g_wqlo);
    cudaGetSymbolAddress((void**)&wkh, g_wkhi); cudaGetSymbolAddress((void**)&wkl, g_wklo);
    cudaGetSymbolAddress((void**)&wvh, g_wvhi); cudaGetSymbolAddress((void**)&wvl, g_wvlo);
    cudaGetSymbolAddress((void**)&woh, g_wohi); cudaGetSymbolAddress((void**)&wol, g_wolo);
    cudaGetSymbolAddress((void**)&wch, g_wchi); cudaGetSymbolAddress((void**)&wcl, g_wclo);
    cudaGetSymbolAddress((void**)&khi, g_khi2); cudaGetSymbolAddress((void**)&klo, g_klo2);
    cudaGetSymbolAddress((void**)&qhi, g_qhi);  cudaGetSymbolAddress((void**)&qlo, g_qlo);
    cudaGetSymbolAddress((void**)&kbh, g_kbhi); cudaGetSymbolAddress((void**)&kbl, g_kblo);
    cudaGetSymbolAddress((void**)&vbh, g_vbhi); cudaGetSymbolAddress((void**)&vbl, g_vblo);
    cudaGetSymbolAddress((void**)&ohi, g_ohi);  cudaGetSymbolAddress((void**)&olo, g_olo);

    cudaFuncSetAttribute(gemm_mma, cudaFuncAttributeMaxDynamicSharedMemorySize, GM_SMEM);
    cudaFuncSetAttribute(attn_mma, cudaFuncAttributeMaxDynamicSharedMemorySize, FA_SMEM);

    // conversions
    { int n = BB * TT * DD; split_kernel<<<(n + 255) / 256, 256>>>(x, xhi, xlo, n); }
    { int n = 4 * DD * DD;
      split4_kernel<<<n / 256, 256>>>(Wq, Wk, Wv, Wo,
                                      wqh, wql, wkh, wkl, wvh, wvl, woh, wol); }
    { int n = DD * DD * 3; repack_conv_kernel<<<(n + 255) / 256, 256>>>(Wconv, wch, wcl); }
    { int n = BB * DD; copy_row0_kernel<<<(n + 255) / 256, 256>>>(x, khi, klo); }

    // conv GEMM -> k_tmp (scatter, bf16 hi/lo out)
    {
        dim3 grid(DD / GM_BN, (BB * TC + GM_BM - 1) / GM_BM, 1);
        gemm_mma<<<grid, 256, GM_SMEM>>>(xhi, xlo, 3L * DD, wch, wcl, nullptr, nullptr, nullptr,
                                         nullptr, khi, klo, nullptr, nullptr,
                                         BB * TC, 3 * DD, 1, 1.f);
    }
    // Q = (x @ Wq^T) * 0.125 -> bf16 hi/lo
    {
        dim3 grid(DD / GM_BN, (BB * TT + GM_BM - 1) / GM_BM, 1);
        gemm_mma<<<grid, 256, GM_SMEM>>>(xhi, xlo, (long)DD, wqh, wql, nullptr, nullptr, nullptr,
                                         nullptr, qhi, qlo, nullptr, nullptr,
                                         BB * TT, DD, 2, 0.125f);
    }
    // K, V = k_tmp @ Wk^T / Wv^T -> bf16 hi/lo (fused launch, z picks weight)
    {
        dim3 grid(DD / GM_BN, (BB * TKK + GM_BM - 1) / GM_BM, 2);
        gemm_mma<<<grid, 256, GM_SMEM>>>(khi, klo, (long)DD, wkh, wkl, wvh, wvl, nullptr,
                                         nullptr, kbh, kbl, vbh, vbl,
                                         BB * TKK, DD, 2, 1.f);
    }
    // attention (tensor-core)
    {
        dim3 grid(TT / FA_BQ, BB * HH);                        // (24, 64)
        attn_mma<<<grid, 256, FA_SMEM>>>(qhi, qlo, kbh, kbl, vbh, vbl, ohi, olo);
    }
    // out = o @ Wo^T + bo
    {
        dim3 grid(DD / GM_BN, (BB * TT + GM_BM - 1) / GM_BM, 1);
        gemm_mma<<<grid, 256, GM_SMEM>>>(ohi, olo, (long)DD, woh, wol, nullptr, nullptr, bo,
                                         out, nullptr, nullptr, nullptr, nullptr,
                                         BB * TT, DD, 0, 1.f);
    }
}

// round 12
// speedup vs baseline: 1.1586x; 1.1518x over previous
#include <cuda_runtime.h>
#include <cuda_bf16.h>
#include <cstdint>
#include <math.h>

// Problem dims
#define BB 4
#define TT 3072
#define DD 1024
#define HH 16
#define HD 64
#define TC 1024          // conv outputs per batch
#define TKK 1025         // k_tmp rows per batch

// ---------------- static scratch ----------------
__device__ __nv_bfloat16 g_xhi[BB * TT * DD], g_xlo[BB * TT * DD];
__device__ __nv_bfloat16 g_wqhi[DD * DD], g_wqlo[DD * DD];
__device__ __nv_bfloat16 g_wkhi[DD * DD], g_wklo[DD * DD];
__device__ __nv_bfloat16 g_wvhi[DD * DD], g_wvlo[DD * DD];
__device__ __nv_bfloat16 g_wohi[DD * DD], g_wolo[DD * DD];
__device__ __nv_bfloat16 g_wchi[DD * 3 * DD], g_wclo[DD * 3 * DD];
__device__ __nv_bfloat16 g_khi2[BB * TKK * DD], g_klo2[BB * TKK * DD];  // k_tmp hi/lo
__device__ __nv_bfloat16 g_qhi[BB * TT * DD], g_qlo[BB * TT * DD];      // Q (pre-scaled)
__device__ __nv_bfloat16 g_kbhi[BB * TKK * DD], g_kblo[BB * TKK * DD];  // K proj
__device__ __nv_bfloat16 g_vbhi[BB * TKK * DD], g_vblo[BB * TKK * DD];  // V proj
__device__ __nv_bfloat16 g_ohi[BB * TT * DD], g_olo[BB * TT * DD];      // attn out

// ---------------- helpers ----------------
__device__ __forceinline__ uint32_t smem_u32(const void* p) {
    uint32_t a;
    asm("{ .reg .u64 t; cvta.to.shared.u64 t, %1; cvt.u32.u64 %0, t; }" : "=r"(a) : "l"(p));
    return a;
}
__device__ __forceinline__ void ldsm4(uint32_t* r, uint32_t addr) {
    asm volatile("ldmatrix.sync.aligned.m8n8.x4.shared.b16 {%0,%1,%2,%3}, [%4];"
        : "=r"(r[0]), "=r"(r[1]), "=r"(r[2]), "=r"(r[3]) : "r"(addr));
}
__device__ __forceinline__ void ldsm4t(uint32_t* r, uint32_t addr) {
    asm volatile("ldmatrix.sync.aligned.m8n8.x4.trans.shared.b16 {%0,%1,%2,%3}, [%4];"
        : "=r"(r[0]), "=r"(r[1]), "=r"(r[2]), "=r"(r[3]) : "r"(addr));
}
__device__ __forceinline__ void mma16816(float* c, const uint32_t* a, uint32_t b0, uint32_t b1) {
    asm volatile("mma.sync.aligned.m16n8k16.row.col.f32.bf16.bf16.f32 "
        "{%0,%1,%2,%3}, {%4,%5,%6,%7}, {%8,%9}, {%0,%1,%2,%3};"
        : "+f"(c[0]), "+f"(c[1]), "+f"(c[2]), "+f"(c[3])
        : "r"(a[0]), "r"(a[1]), "r"(a[2]), "r"(a[3]), "r"(b0), "r"(b1));
}
__device__ __forceinline__ uint32_t packbf2(float x, float y) {
    uint32_t lo = __bfloat16_as_ushort(__float2bfloat16(x));
    uint32_t hi = __bfloat16_as_ushort(__float2bfloat16(y));
    return lo | (hi << 16);
}
__device__ __forceinline__ float bfres(float v) {   // v - bf16(v)
    return v - __bfloat162float(__float2bfloat16(v));
}

// ---------------- vectorized split / repack kernels ----------------
// generic: 4 floats per thread -> 4 bf16 hi + 4 bf16 lo
__global__ void splitv_kernel(const float* __restrict__ s, __nv_bfloat16* __restrict__ hi,
                              __nv_bfloat16* __restrict__ lo, int n4) {
    int i = blockIdx.x * 256 + threadIdx.x;
    if (i >= n4) return;
    float4 v = ((const float4*)s)[i];
    uint2 H, L;
    H.x = packbf2(v.x, v.y);
    H.y = packbf2(v.z, v.w);
    L.x = packbf2(bfres(v.x), bfres(v.y));
    L.y = packbf2(bfres(v.z), bfres(v.w));
    ((uint2*)hi)[i] = H;
    ((uint2*)lo)[i] = L;
}
// 4 weight matrices, 4 floats/thread; 1<<18 float4 per matrix
__global__ void split4v_kernel(const float* __restrict__ w0, const float* __restrict__ w1,
                               const float* __restrict__ w2, const float* __restrict__ w3,
                               __nv_bfloat16* __restrict__ h0, __nv_bfloat16* __restrict__ l0,
                               __nv_bfloat16* __restrict__ h1, __nv_bfloat16* __restrict__ l1,
                               __nv_bfloat16* __restrict__ h2, __nv_bfloat16* __restrict__ l2,
                               __nv_bfloat16* __restrict__ h3, __nv_bfloat16* __restrict__ l3) {
    int i = blockIdx.x * 256 + threadIdx.x;      // 0 .. 4*(1<<18)-1
    int w = i >> 18, j = i & ((1 << 18) - 1);
    const float* s = (w == 0) ? w0 : (w == 1) ? w1 : (w == 2) ? w2 : w3;
    __nv_bfloat16* hp = (w == 0) ? h0 : (w == 1) ? h1 : (w == 2) ? h2 : h3;
    __nv_bfloat16* lp = (w == 0) ? l0 : (w == 1) ? l1 : (w == 2) ? l2 : l3;
    float4 v = ((const float4*)s)[j];
    uint2 H, L;
    H.x = packbf2(v.x, v.y);
    H.y = packbf2(v.z, v.w);
    L.x = packbf2(bfres(v.x), bfres(v.y));
    L.y = packbf2(bfres(v.z), bfres(v.w));
    ((uint2*)hp)[j] = H;
    ((uint2*)lp)[j] = L;
}
// conv repack: thread = (o, block of 4 i's); reads 12 contiguous floats = all 3 kw for 4 i's
__global__ void repack_convv_kernel(const float* __restrict__ W, __nv_bfloat16* __restrict__ hi,
                                    __nv_bfloat16* __restrict__ lo) {
    int t = blockIdx.x * 256 + threadIdx.x;      // 0 .. 1024*256-1
    int o = t >> 8;
    int ib = t & 255;                            // i0 = 4*ib
    const float4* src = (const float4*)(W + (long)o * 3072 + ib * 12);
    float4 a = src[0], b4 = src[1], c4 = src[2];
    float w[12] = {a.x, a.y, a.z, a.w, b4.x, b4.y, b4.z, b4.w, c4.x, c4.y, c4.z, c4.w};
#pragma unroll
    for (int kw = 0; kw < 3; kw++) {
        float v0 = w[kw], v1 = w[kw + 3], v2 = w[kw + 6], v3 = w[kw + 9];
        long d = (long)o * 3072 + kw * 1024 + 4 * ib;
        uint2 H, L;
        H.x = packbf2(v0, v1); H.y = packbf2(v2, v3);
        L.x = packbf2(bfres(v0), bfres(v1)); L.y = packbf2(bfres(v2), bfres(v3));
        *(uint2*)(hi + d) = H;
        *(uint2*)(lo + d) = L;
    }
}
__global__ void copy_row0v_kernel(const float* __restrict__ x, __nv_bfloat16* __restrict__ khi,
                                  __nv_bfloat16* __restrict__ klo) {
    int i = blockIdx.x * 256 + threadIdx.x;      // 0 .. BB*DD/4-1
    int b = i / (DD / 4), j = i % (DD / 4);
    float4 v = ((const float4*)(x + (long)b * TT * DD))[j];
    uint2 H, L;
    H.x = packbf2(v.x, v.y); H.y = packbf2(v.z, v.w);
    L.x = packbf2(bfres(v.x), bfres(v.y)); L.y = packbf2(bfres(v.z), bfres(v.w));
    ((uint2*)(khi + (long)b * TKK * DD))[j] = H;
    ((uint2*)(klo + (long)b * TKK * DD))[j] = L;
}

// ---------------- mma.sync GEMM: C[M,1024] = A @ B^T (bf16x3 split) ----------------
// R9 form: LDG->STS double buffer, 80KB smem -> 2 CTAs/SM.
// outmap 0: fp32 Cf (+bias).  outmap 1: conv scatter -> bf16 hi/lo.  outmap 2: bf16 hi/lo (scaled).
#define GM_BM 128
#define GM_BN 128
#define GM_BK 32
#define GM_ROWB 80
#define GM_TILE (128 * GM_ROWB)        // 10240
#define GM_STAGE (4 * GM_TILE)         // 40960
#define GM_SMEM (2 * GM_STAGE)         // 81920

__global__ void __launch_bounds__(256)
gemm_mma(const __nv_bfloat16* __restrict__ Ahi, const __nv_bfloat16* __restrict__ Alo, long lda,
         const __nv_bfloat16* __restrict__ Bhi, const __nv_bfloat16* __restrict__ Blo,
         const float* __restrict__ bias,
         float* __restrict__ Cf, __nv_bfloat16* __restrict__ Chi, __nv_bfloat16* __restrict__ Clo,
         int M, int K, int outmap, float oscale)
{
    extern __shared__ char smem[];
    const uint32_t sb = smem_u32(smem);
    const int tid = threadIdx.x;
    const int wid = tid >> 5, lane = tid & 31;
    const int bm = blockIdx.y * GM_BM, bn = blockIdx.x * GM_BN;
    const int mbase = (wid & 3) * 32;
    const int nbase = (wid >> 2) * 64;

    const int grp = lane >> 3, rowg = lane & 7;
    const int a_row = (grp & 1) * 8 + rowg;
    const int a_koff = (grp >> 1) * 16;
    const int b_row = (grp >> 1) * 8 + rowg;
    const int b_koff = (grp & 1) * 16;

    float acc[2][8][4];
#pragma unroll
    for (int i = 0; i < 2; i++)
#pragma unroll
        for (int j = 0; j < 8; j++)
#pragma unroll
            for (int k = 0; k < 4; k++) acc[i][j][k] = 0.f;

    auto load_stage = [&](int stg, int c) {
        char* base = smem + stg * GM_STAGE;
        const int k0 = c * GM_BK;
#pragma unroll
        for (int it = 0; it < 8; it++) {
            int i = it * 256 + tid;
            int t = i >> 9;               // 0 Ahi, 1 Alo, 2 Bhi, 3 Blo
            int r = (i >> 2) & 127;
            int s = i & 3;
            uint4 v = make_uint4(0, 0, 0, 0);
            if (t < 2) {
                int row = bm + r;
                if (row < M) {
                    const __nv_bfloat16* src = t ? Alo : Ahi;
                    v = *(const uint4*)(src + (long)row * lda + k0 + s * 8);
                }
            } else {
                const __nv_bfloat16* src = (t == 3) ? Blo : Bhi;
                v = *(const uint4*)(src + (long)(bn + r) * K + k0 + s * 8);
            }
            *(uint4*)(base + t * GM_TILE + r * GM_ROWB + s * 16) = v;
        }
    };

    const int nch = K / GM_BK;
    load_stage(0, 0);
    __syncthreads();

    for (int c = 0; c < nch; c++) {
        const uint32_t st = sb + (c & 1) * GM_STAGE;
        if (c + 1 < nch) load_stage((c + 1) & 1, c + 1);
#pragma unroll
        for (int ks = 0; ks < 2; ks++) {
            const int koff = ks * 32;
            uint32_t ah[2][4], al[2][4];
#pragma unroll
            for (int mf = 0; mf < 2; mf++) {
                uint32_t ra = st + (uint32_t)((mbase + mf * 16 + a_row) * GM_ROWB + koff + a_koff);
                ldsm4(ah[mf], ra);
                ldsm4(al[mf], ra + GM_TILE);
            }
            uint32_t bh[4][4], bl[4][4];
#pragma unroll
            for (int nf = 0; nf < 4; nf++) {
                uint32_t rb = st + 2 * GM_TILE +
                              (uint32_t)((nbase + nf * 16 + b_row) * GM_ROWB + koff + b_koff);
                ldsm4(bh[nf], rb);
                ldsm4(bl[nf], rb + GM_TILE);
            }
#pragma unroll
            for (int mf = 0; mf < 2; mf++)
#pragma unroll
                for (int nf = 0; nf < 4; nf++)
#pragma unroll
                    for (int h = 0; h < 2; h++) {
                        float* a4 = acc[mf][nf * 2 + h];
                        mma16816(a4, ah[mf], bh[nf][h * 2], bh[nf][h * 2 + 1]);
                        mma16816(a4, ah[mf], bl[nf][h * 2], bl[nf][h * 2 + 1]);
                        mma16816(a4, al[mf], bh[nf][h * 2], bh[nf][h * 2 + 1]);
                    }
        }
        __syncthreads();
    }

    // epilogue
#pragma unroll
    for (int mf = 0; mf < 2; mf++)
#pragma unroll
        for (int nf = 0; nf < 8; nf++) {
            const int row0 = bm + mbase + mf * 16 + (lane >> 2);
            const int col = bn + nbase + nf * 8 + (lane & 3) * 2;
            const float* a4 = acc[mf][nf];
#pragma unroll
            for (int half = 0; half < 2; half++) {
                int row = row0 + half * 8;
                if (row >= M) continue;
                float v0 = a4[half * 2 + 0], v1 = a4[half * 2 + 1];
                if (outmap == 1) {
                    long crow = (long)row + row / TC + 1;
                    *(uint32_t*)(Chi + crow * DD + col) = packbf2(v0, v1);
                    *(uint32_t*)(Clo + crow * DD + col) = packbf2(bfres(v0), bfres(v1));
                } else if (outmap == 2) {
                    v0 *= oscale; v1 *= oscale;
                    *(uint32_t*)(Chi + (long)row * DD + col) = packbf2(v0, v1);
                    *(uint32_t*)(Clo + (long)row * DD + col) = packbf2(bfres(v0), bfres(v1));
                } else {
                    if (bias) { v0 += bias[col]; v1 += bias[col + 1]; }
                    *(float2*)(Cf + (long)row * DD + col) = make_float2(v0, v1);
                }
            }
        }
}

// ---------------- mma.sync flash attention, 3k<=q mask ----------------
// 128 queries/CTA (8 warps x 16 rows), 64-key tiles, cp.async double buffer.
#define FA_BQ 128
#define FA_BK 64
#define FA_ROWB 144
#define FA_TILE (64 * FA_ROWB)     // 9216
#define FA_STAGE (4 * FA_TILE)     // 36864 : Khi, Klo, Vhi, Vlo
#define FA_SMEM (2 * FA_STAGE)     // 73728

__global__ void __launch_bounds__(256)
attn_mma(const __nv_bfloat16* __restrict__ Qhi, const __nv_bfloat16* __restrict__ Qlo,
         const __nv_bfloat16* __restrict__ Khi, const __nv_bfloat16* __restrict__ Klo,
         const __nv_bfloat16* __restrict__ Vhi, const __nv_bfloat16* __restrict__ Vlo,
         __nv_bfloat16* __restrict__ Ohi, __nv_bfloat16* __restrict__ Olo)
{
    extern __shared__ char smem[];
    const uint32_t sb = smem_u32(smem);
    const int tid = threadIdx.x, wid = tid >> 5, lane = tid & 31;
    const int bh = blockIdx.y, b = bh >> 4, h = bh & 15;
    const int q0 = blockIdx.x * FA_BQ;

    const int grp = lane >> 3, rowg = lane & 7;
    const int a_row = (grp & 1) * 8 + rowg, a_koff = (grp >> 1) * 16;
    const int b_row = (grp >> 1) * 8 + rowg, b_koff = (grp & 1) * 16;
    const int v_row = (grp & 1) * 8 + rowg, v_koff = (grp >> 1) * 16;
    const int lq = lane >> 2, lc = (lane & 3) * 2;
    const int qrow0 = q0 + wid * 16 + lq;
    const int qrow1 = qrow0 + 8;

    // ---- stage Q (hi at 0, lo at +18432), extract fragments ----
#pragma unroll
    for (int it = 0; it < 8; it++) {
        int idx = it * 256 + tid;
        int t = idx >> 10, r = (idx >> 3) & 127, s = idx & 7;
        const __nv_bfloat16* src = t ? Qlo : Qhi;
        uint4 v = *(const uint4*)(src + (long)(b * TT + q0 + r) * DD + h * HD + s * 8);
        *(uint4*)(smem + t * 18432 + r * FA_ROWB + s * 16) = v;
    }
    __syncthreads();
    uint32_t qh[4][4], ql[4][4];
#pragma unroll
    for (int ks = 0; ks < 4; ks++) {
        uint32_t ra = sb + (uint32_t)((wid * 16 + a_row) * FA_ROWB + ks * 32 + a_koff);
        ldsm4(qh[ks], ra);
        ldsm4(ql[ks], ra + 18432);
    }
    __syncthreads();

    const int kmax = (q0 + FA_BQ - 1) / 3;
    const int nt = kmax / FA_BK + 1;

    auto load_kv = [&](int stg, int t) {
        const int kt = t * FA_BK;
        const uint32_t dst0 = sb + stg * FA_STAGE;
#pragma unroll
        for (int it = 0; it < 8; it++) {
            int idx = it * 256 + tid;
            int tt = idx >> 9, r = (idx >> 3) & 63, s = idx & 7;
            int kid = kt + r;
            if (kid > TKK - 1) kid = TKK - 1;
            const __nv_bfloat16* src = (tt == 0) ? Khi : (tt == 1) ? Klo : (tt == 2) ? Vhi : Vlo;
            const __nv_bfloat16* sp = src + (long)(b * TKK + kid) * DD + h * HD + s * 8;
            uint32_t dp = dst0 + (uint32_t)(tt * FA_TILE + r * FA_ROWB + s * 16);
            asm volatile("cp.async.cg.shared.global [%0], [%1], 16;" :: "r"(dp), "l"(sp));
        }
        asm volatile("cp.async.commit_group;" ::: "memory");
    };

    float Oa[8][4];
#pragma unroll
    for (int i = 0; i < 8; i++)
#pragma unroll
        for (int j = 0; j < 4; j++) Oa[i][j] = 0.f;
    float m0 = -1e30f, m1 = -1e30f, l0 = 0.f, l1 = 0.f;

    load_kv(0, 0);

    for (int t = 0; t < nt; t++) {
        const int stg = t & 1;
        if (t + 1 < nt) {
            load_kv(stg ^ 1, t + 1);
            asm volatile("cp.async.wait_group 1;" ::: "memory");
        } else {
            asm volatile("cp.async.wait_group 0;" ::: "memory");
        }
        __syncthreads();

        const int kt = t * FA_BK;
        const uint32_t stk = sb + stg * FA_STAGE;
        const uint32_t stv = stk + 2 * FA_TILE;

        // ---- S = Qs @ K^T (split) ----
        float S[8][4];
#pragma unroll
        for (int i = 0; i < 8; i++)
#pragma unroll
            for (int j = 0; j < 4; j++) S[i][j] = 0.f;

#pragma unroll
        for (int ng = 0; ng < 4; ng++) {
#pragma unroll
            for (int ks = 0; ks < 4; ks++) {
                uint32_t kh[4], kl[4];
                uint32_t rb = stk + (uint32_t)((ng * 16 + b_row) * FA_ROWB + ks * 32 + b_koff);
                ldsm4(kh, rb);
                ldsm4(kl, rb + FA_TILE);
                mma16816(S[2 * ng],     qh[ks], kh[0], kh[1]);
                mma16816(S[2 * ng + 1], qh[ks], kh[2], kh[3]);
                mma16816(S[2 * ng],     qh[ks], kl[0], kl[1]);
                mma16816(S[2 * ng + 1], qh[ks], kl[2], kl[3]);
                mma16816(S[2 * ng],     ql[ks], kh[0], kh[1]);
                mma16816(S[2 * ng + 1], ql[ks], kh[2], kh[3]);
            }
        }

        // ---- mask + online softmax ----
        float mx0 = -1e30f, mx1 = -1e30f;
#pragma unroll
        for (int nf = 0; nf < 8; nf++) {
            int key = kt + nf * 8 + lc;
            if (3 * key > qrow0)       S[nf][0] = -1e30f;
            if (3 * (key + 1) > qrow0) S[nf][1] = -1e30f;
            if (3 * key > qrow1)       S[nf][2] = -1e30f;
            if (3 * (key + 1) > qrow1) S[nf][3] = -1e30f;
            mx0 = fmaxf(mx0, fmaxf(S[nf][0], S[nf][1]));
            mx1 = fmaxf(mx1, fmaxf(S[nf][2], S[nf][3]));
        }
        mx0 = fmaxf(mx0, __shfl_xor_sync(0xFFFFFFFF, mx0, 1));
        mx0 = fmaxf(mx0, __shfl_xor_sync(0xFFFFFFFF, mx0, 2));
        mx1 = fmaxf(mx1, __shfl_xor_sync(0xFFFFFFFF, mx1, 1));
        mx1 = fmaxf(mx1, __shfl_xor_sync(0xFFFFFFFF, mx1, 2));
        float mn0 = fmaxf(m0, mx0), mn1 = fmaxf(m1, mx1);
        float c0 = __expf(m0 - mn0), c1 = __expf(m1 - mn1);

        float ls0 = 0.f, ls1 = 0.f;
#pragma unroll
        for (int nf = 0; nf < 8; nf++) {
            S[nf][0] = __expf(S[nf][0] - mn0);
            S[nf][1] = __expf(S[nf][1] - mn0);
            S[nf][2] = __expf(S[nf][2] - mn1);
            S[nf][3] = __expf(S[nf][3] - mn1);
            ls0 += S[nf][0] + S[nf][1];
            ls1 += S[nf][2] + S[nf][3];
        }
        ls0 += __shfl_xor_sync(0xFFFFFFFF, ls0, 1);
        ls0 += __shfl_xor_sync(0xFFFFFFFF, ls0, 2);
        ls1 += __shfl_xor_sync(0xFFFFFFFF, ls1, 1);
        ls1 += __shfl_xor_sync(0xFFFFFFFF, ls1, 2);
        l0 = l0 * c0 + ls0;
        l1 = l1 * c1 + ls1;
        m0 = mn0; m1 = mn1;

#pragma unroll
        for (int nf = 0; nf < 8; nf++) {
            Oa[nf][0] *= c0; Oa[nf][1] *= c0;
            Oa[nf][2] *= c1; Oa[nf][3] *= c1;
        }

        // ---- O += P @ V (P split hi/lo, V split hi/lo) ----
#pragma unroll
        for (int g = 0; g < 4; g++) {
            uint32_t ph[4], pl[4];
            float p00 = S[2 * g][0], p01 = S[2 * g][1], p02 = S[2 * g][2], p03 = S[2 * g][3];
            float p10 = S[2 * g + 1][0], p11 = S[2 * g + 1][1], p12 = S[2 * g + 1][2], p13 = S[2 * g + 1][3];
            ph[0] = packbf2(p00, p01); ph[1] = packbf2(p02, p03);
            ph[2] = packbf2(p10, p11); ph[3] = packbf2(p12, p13);
            pl[0] = packbf2(bfres(p00), bfres(p01)); pl[1] = packbf2(bfres(p02), bfres(p03));
            pl[2] = packbf2(bfres(p10), bfres(p11)); pl[3] = packbf2(bfres(p12), bfres(p13));
#pragma unroll
            for (int dg = 0; dg < 4; dg++) {
                uint32_t vh[4], vl[4];
                uint32_t rv = stv + (uint32_t)((g * 16 + v_row) * FA_ROWB + dg * 32 + v_koff);
                ldsm4t(vh, rv);
                ldsm4t(vl, rv + FA_TILE);
                mma16816(Oa[2 * dg],     ph, vh[0], vh[1]);
                mma16816(Oa[2 * dg + 1], ph, vh[2], vh[3]);
                mma16816(Oa[2 * dg],     ph, vl[0], vl[1]);
                mma16816(Oa[2 * dg + 1], ph, vl[2], vl[3]);
                mma16816(Oa[2 * dg],     pl, vh[0], vh[1]);
                mma16816(Oa[2 * dg + 1], pl, vh[2], vh[3]);
            }
        }
        __syncthreads();
    }

    // ---- normalize + store bf16 hi/lo ----
    const float inv0 = 1.f / l0, inv1 = 1.f / l1;
#pragma unroll
    for (int nf = 0; nf < 8; nf++) {
#pragma unroll
        for (int r = 0; r < 2; r++) {
            int row = (r == 0) ? qrow0 : qrow1;
            float inv = (r == 0) ? inv0 : inv1;
            float v0 = Oa[nf][r * 2 + 0] * inv;
            float v1 = Oa[nf][r * 2 + 1] * inv;
            long base = (long)(b * TT + row) * DD + h * HD + nf * 8 + lc;
            *(uint32_t*)(Ohi + base) = packbf2(v0, v1);
            *(uint32_t*)(Olo + base) = packbf2(bfres(v0), bfres(v1));
        }
    }
}

// ---------------- launch ----------------
extern "C" void kernel_launch(void* const* d_in, const int* in_sizes, int n_in,
                              void* d_out, int out_size)
{
    const float* x     = (const float*)d_in[0];
    const float* Wq    = (const float*)d_in[1];
    const float* Wk    = (const float*)d_in[2];
    const float* Wv    = (const float*)d_in[3];
    const float* Wo    = (const float*)d_in[4];
    const float* bo    = (const float*)d_in[5];
    const float* Wconv = (const float*)d_in[6];
    float* out = (float*)d_out;

    __nv_bfloat16 *xhi, *xlo, *wqh, *wql, *wkh, *wkl, *wvh, *wvl, *woh, *wol, *wch, *wcl;
    __nv_bfloat16 *khi, *klo, *qhi, *qlo, *kbh, *kbl, *vbh, *vbl, *ohi, *olo;
    cudaGetSymbolAddress((void**)&xhi, g_xhi);  cudaGetSymbolAddress((void**)&xlo, g_xlo);
    cudaGetSymbolAddress((void**)&wqh, g_wqhi); cudaGetSymbolAddress((void**)&wql, g_wqlo);
    cudaGetSymbolAddress((void**)&wkh, g_wkhi); cudaGetSymbolAddress((void**)&wkl, g_wklo);
    cudaGetSymbolAddress((void**)&wvh, g_wvhi); cudaGetSymbolAddress((void**)&wvl, g_wvlo);
    cudaGetSymbolAddress((void**)&woh, g_wohi); cudaGetSymbolAddress((void**)&wol, g_wolo);
    cudaGetSymbolAddress((void**)&wch, g_wchi); cudaGetSymbolAddress((void**)&wcl, g_wclo);
    cudaGetSymbolAddress((void**)&khi, g_khi2); cudaGetSymbolAddress((void**)&klo, g_klo2);
    cudaGetSymbolAddress((void**)&qhi, g_qhi);  cudaGetSymbolAddress((void**)&qlo, g_qlo);
    cudaGetSymbolAddress((void**)&kbh, g_kbhi); cudaGetSymbolAddress((void**)&kbl, g_kblo);
    cudaGetSymbolAddress((void**)&vbh, g_vbhi); cudaGetSymbolAddress((void**)&vbl, g_vblo);
    cudaGetSymbolAddress((void**)&ohi, g_ohi);  cudaGetSymbolAddress((void**)&olo, g_olo);

    cudaFuncSetAttribute(gemm_mma, cudaFuncAttributeMaxDynamicSharedMemorySize, GM_SMEM);
    cudaFuncSetAttribute(attn_mma, cudaFuncAttributeMaxDynamicSharedMemorySize, FA_SMEM);

    // conversions (vectorized)
    { int n4 = BB * TT * DD / 4;                      // 3145728
      splitv_kernel<<<n4 / 256, 256>>>(x, xhi, xlo, n4); }
    { int n = 4 * (DD * DD / 4);                      // 1048576
      split4v_kernel<<<n / 256, 256>>>(Wq, Wk, Wv, Wo,
                                       wqh, wql, wkh, wkl, wvh, wvl, woh, wol); }
    { repack_convv_kernel<<<(DD * 256) / 256, 256>>>(Wconv, wch, wcl); }   // 1024 blocks
    { copy_row0v_kernel<<<(BB * DD / 4) / 256, 256>>>(x, khi, klo); }      // 4 blocks

    // conv GEMM -> k_tmp (scatter, bf16 hi/lo out)
    {
        dim3 grid(DD / GM_BN, (BB * TC + GM_BM - 1) / GM_BM);
        gemm_mma<<<grid, 256, GM_SMEM>>>(xhi, xlo, 3L * DD, wch, wcl, nullptr,
                                         nullptr, khi, klo, BB * TC, 3 * DD, 1, 1.f);
    }
    // Q = (x @ Wq^T) * 0.125 -> bf16 hi/lo
    {
        dim3 grid(DD / GM_BN, (BB * TT + GM_BM - 1) / GM_BM);
        gemm_mma<<<grid, 256, GM_SMEM>>>(xhi, xlo, (long)DD, wqh, wql, nullptr,
                                         nullptr, qhi, qlo, BB * TT, DD, 2, 0.125f);
    }
    // K, V = k_tmp @ Wk^T / Wv^T -> bf16 hi/lo
    {
        dim3 grid(DD / GM_BN, (BB * TKK + GM_BM - 1) / GM_BM);
        gemm_mma<<<grid, 256, GM_SMEM>>>(khi, klo, (long)DD, wkh, wkl, nullptr,
                                         nullptr, kbh, kbl, BB * TKK, DD, 2, 1.f);
        gemm_mma<<<grid, 256, GM_SMEM>>>(khi, klo, (long)DD, wvh, wvl, nullptr,
                                         nullptr, vbh, vbl, BB * TKK, DD, 2, 1.f);
    }
    // attention (tensor-core)
    {
        dim3 grid(TT / FA_BQ, BB * HH);                        // (24, 64)
        attn_mma<<<grid, 256, FA_SMEM>>>(qhi, qlo, kbh, kbl, vbh, vbl, ohi, olo);
    }
    // out = o @ Wo^T + bo
    {
        dim3 grid(DD / GM_BN, (BB * TT + GM_BM - 1) / GM_BM);
        gemm_mma<<<grid, 256, GM_SMEM>>>(ohi, olo, (long)DD, woh, wol, bo,
                                         out, nullptr, nullptr, BB * TT, DD, 0, 1.f);
    }
}

// round 14
// speedup vs baseline: 1.5187x; 1.3108x over previous
#include <cuda_runtime.h>
#include <cuda_fp16.h>
#include <cstdint>
#include <math.h>

// Problem dims
#define BB 4
#define TT 3072
#define DD 1024
#define HH 16
#define HD 64
#define TC 1024          // conv outputs per batch
#define TKK 1025         // k_tmp rows per batch

// ---------------- static scratch (fp16) ----------------
__device__ __half g_xhi[BB * TT * DD], g_xlo[BB * TT * DD];
__device__ __half g_wqhi[DD * DD], g_wqlo[DD * DD];
__device__ __half g_wkhi[DD * DD], g_wklo[DD * DD];
__device__ __half g_wvhi[DD * DD], g_wvlo[DD * DD];
__device__ __half g_wohi[DD * DD], g_wolo[DD * DD];
__device__ __half g_wchi[DD * 3 * DD], g_wclo[DD * 3 * DD];
__device__ __half g_khi2[BB * TKK * DD], g_klo2[BB * TKK * DD];  // k_tmp hi/lo
__device__ __half g_qhi[BB * TT * DD], g_qlo[BB * TT * DD];      // Q (pre-scaled) hi/lo
__device__ __half g_kb[BB * TKK * DD];                           // K proj (single fp16)
__device__ __half g_vb[BB * TKK * DD];                           // V proj (single fp16)
__device__ __half g_ohi[BB * TT * DD], g_olo[BB * TT * DD];      // attn out hi/lo

// ---------------- helpers ----------------
__device__ __forceinline__ uint32_t smem_u32(const void* p) {
    uint32_t a;
    asm("{ .reg .u64 t; cvta.to.shared.u64 t, %1; cvt.u32.u64 %0, t; }" : "=r"(a) : "l"(p));
    return a;
}
__device__ __forceinline__ void ldsm4(uint32_t* r, uint32_t addr) {
    asm volatile("ldmatrix.sync.aligned.m8n8.x4.shared.b16 {%0,%1,%2,%3}, [%4];"
        : "=r"(r[0]), "=r"(r[1]), "=r"(r[2]), "=r"(r[3]) : "r"(addr));
}
__device__ __forceinline__ void ldsm4t(uint32_t* r, uint32_t addr) {
    asm volatile("ldmatrix.sync.aligned.m8n8.x4.trans.shared.b16 {%0,%1,%2,%3}, [%4];"
        : "=r"(r[0]), "=r"(r[1]), "=r"(r[2]), "=r"(r[3]) : "r"(addr));
}
__device__ __forceinline__ void mma16816(float* c, const uint32_t* a, uint32_t b0, uint32_t b1) {
    asm volatile("mma.sync.aligned.m16n8k16.row.col.f32.f16.f16.f32 "
        "{%0,%1,%2,%3}, {%4,%5,%6,%7}, {%8,%9}, {%0,%1,%2,%3};"
        : "+f"(c[0]), "+f"(c[1]), "+f"(c[2]), "+f"(c[3])
        : "r"(a[0]), "r"(a[1]), "r"(a[2]), "r"(a[3]), "r"(b0), "r"(b1));
}
__device__ __forceinline__ uint32_t packh2(float x, float y) {
    __half2 h = __floats2half2_rn(x, y);
    return *(uint32_t*)&h;
}
__device__ __forceinline__ float hres(float v) {   // v - fp16(v)
    return v - __half2float(__float2half_rn(v));
}

// ---------------- vectorized split / repack kernels ----------------
__global__ void splitv_kernel(const float* __restrict__ s, __half* __restrict__ hi,
                              __half* __restrict__ lo, int n4) {
    int i = blockIdx.x * 256 + threadIdx.x;
    if (i >= n4) return;
    float4 v = ((const float4*)s)[i];
    uint2 H, L;
    H.x = packh2(v.x, v.y);
    H.y = packh2(v.z, v.w);
    L.x = packh2(hres(v.x), hres(v.y));
    L.y = packh2(hres(v.z), hres(v.w));
    ((uint2*)hi)[i] = H;
    ((uint2*)lo)[i] = L;
}
__global__ void split4v_kernel(const float* __restrict__ w0, const float* __restrict__ w1,
                               const float* __restrict__ w2, const float* __restrict__ w3,
                               __half* __restrict__ h0, __half* __restrict__ l0,
                               __half* __restrict__ h1, __half* __restrict__ l1,
                               __half* __restrict__ h2, __half* __restrict__ l2,
                               __half* __restrict__ h3, __half* __restrict__ l3) {
    int i = blockIdx.x * 256 + threadIdx.x;      // 0 .. 4*(1<<18)-1
    int w = i >> 18, j = i & ((1 << 18) - 1);
    const float* s = (w == 0) ? w0 : (w == 1) ? w1 : (w == 2) ? w2 : w3;
    __half* hp = (w == 0) ? h0 : (w == 1) ? h1 : (w == 2) ? h2 : h3;
    __half* lp = (w == 0) ? l0 : (w == 1) ? l1 : (w == 2) ? l2 : l3;
    float4 v = ((const float4*)s)[j];
    uint2 H, L;
    H.x = packh2(v.x, v.y);
    H.y = packh2(v.z, v.w);
    L.x = packh2(hres(v.x), hres(v.y));
    L.y = packh2(hres(v.z), hres(v.w));
    ((uint2*)hp)[j] = H;
    ((uint2*)lp)[j] = L;
}
__global__ void repack_convv_kernel(const float* __restrict__ W, __half* __restrict__ hi,
                                    __half* __restrict__ lo) {
    int t = blockIdx.x * 256 + threadIdx.x;      // 0 .. 1024*256-1
    int o = t >> 8;
    int ib = t & 255;                            // i0 = 4*ib
    const float4* src = (const float4*)(W + (long)o * 3072 + ib * 12);
    float4 a = src[0], b4 = src[1], c4 = src[2];
    float w[12] = {a.x, a.y, a.z, a.w, b4.x, b4.y, b4.z, b4.w, c4.x, c4.y, c4.z, c4.w};
#pragma unroll
    for (int kw = 0; kw < 3; kw++) {
        float v0 = w[kw], v1 = w[kw + 3], v2 = w[kw + 6], v3 = w[kw + 9];
        long d = (long)o * 3072 + kw * 1024 + 4 * ib;
        uint2 H, L;
        H.x = packh2(v0, v1); H.y = packh2(v2, v3);
        L.x = packh2(hres(v0), hres(v1)); L.y = packh2(hres(v2), hres(v3));
        *(uint2*)(hi + d) = H;
        *(uint2*)(lo + d) = L;
    }
}
__global__ void copy_row0v_kernel(const float* __restrict__ x, __half* __restrict__ khi,
                                  __half* __restrict__ klo) {
    int i = blockIdx.x * 256 + threadIdx.x;      // 0 .. BB*DD/4-1
    int b = i / (DD / 4), j = i % (DD / 4);
    float4 v = ((const float4*)(x + (long)b * TT * DD))[j];
    uint2 H, L;
    H.x = packh2(v.x, v.y); H.y = packh2(v.z, v.w);
    L.x = packh2(hres(v.x), hres(v.y)); L.y = packh2(hres(v.z), hres(v.w));
    ((uint2*)(khi + (long)b * TKK * DD))[j] = H;
    ((uint2*)(klo + (long)b * TKK * DD))[j] = L;
}

// ---------------- mma.sync GEMM: C[M,1024] = A @ B^T (fp16 split) ----------------
// NPASS=3: ah*bh + ah*bl + al*bh.  NPASS=2: ah*bh + al*bh (B single fp16, Blo unused).
// outmap 0: fp32 Cf (+bias). 1: conv scatter -> fp16 hi/lo. 2: fp16 hi/lo (scaled). 3: single fp16.
#define GM_BM 128
#define GM_BN 128
#define GM_BK 32
#define GM_ROWB 80
#define GM_TILE (128 * GM_ROWB)        // 10240
#define GM_STAGE (4 * GM_TILE)         // 40960
#define GM_SMEM (2 * GM_STAGE)         // 81920

template <int NPASS>
__global__ void __launch_bounds__(256)
gemm_mma(const __half* __restrict__ Ahi, const __half* __restrict__ Alo, long lda,
         const __half* __restrict__ Bhi, const __half* __restrict__ Blo,
         const float* __restrict__ bias,
         float* __restrict__ Cf, __half* __restrict__ Chi, __half* __restrict__ Clo,
         int M, int K, int outmap, float oscale)
{
    extern __shared__ char smem[];
    const uint32_t sb = smem_u32(smem);
    const int tid = threadIdx.x;
    const int wid = tid >> 5, lane = tid & 31;
    const int bm = blockIdx.y * GM_BM, bn = blockIdx.x * GM_BN;
    const int mbase = (wid & 3) * 32;
    const int nbase = (wid >> 2) * 64;

    const int grp = lane >> 3, rowg = lane & 7;
    const int a_row = (grp & 1) * 8 + rowg;
    const int a_koff = (grp >> 1) * 16;
    const int b_row = (grp >> 1) * 8 + rowg;
    const int b_koff = (grp & 1) * 16;

    float acc[2][8][4];
#pragma unroll
    for (int i = 0; i < 2; i++)
#pragma unroll
        for (int j = 0; j < 8; j++)
#pragma unroll
            for (int k = 0; k < 4; k++) acc[i][j][k] = 0.f;

    const int NIT = (NPASS == 3) ? 8 : 6;   // tiles: Ahi, Alo, Bhi, [Blo]
    auto load_stage = [&](int stg, int c) {
        char* base = smem + stg * GM_STAGE;
        const int k0 = c * GM_BK;
#pragma unroll
        for (int it = 0; it < NIT; it++) {
            int i = it * 256 + tid;
            int t = i >> 9;               // 0 Ahi, 1 Alo, 2 Bhi, 3 Blo
            int r = (i >> 2) & 127;
            int s = i & 3;
            uint4 v = make_uint4(0, 0, 0, 0);
            if (t < 2) {
                int row = bm + r;
                if (row < M) {
                    const __half* src = t ? Alo : Ahi;
                    v = *(const uint4*)(src + (long)row * lda + k0 + s * 8);
                }
            } else {
                const __half* src = (t == 3) ? Blo : Bhi;
                v = *(const uint4*)(src + (long)(bn + r) * K + k0 + s * 8);
            }
            *(uint4*)(base + t * GM_TILE + r * GM_ROWB + s * 16) = v;
        }
    };

    const int nch = K / GM_BK;
    load_stage(0, 0);
    __syncthreads();

    for (int c = 0; c < nch; c++) {
        const uint32_t st = sb + (c & 1) * GM_STAGE;
        if (c + 1 < nch) load_stage((c + 1) & 1, c + 1);
#pragma unroll
        for (int ks = 0; ks < 2; ks++) {
            const int koff = ks * 32;
            uint32_t ah[2][4], al[2][4];
#pragma unroll
            for (int mf = 0; mf < 2; mf++) {
                uint32_t ra = st + (uint32_t)((mbase + mf * 16 + a_row) * GM_ROWB + koff + a_koff);
                ldsm4(ah[mf], ra);
                ldsm4(al[mf], ra + GM_TILE);
            }
            uint32_t bh[4][4], bl[4][4];
#pragma unroll
            for (int nf = 0; nf < 4; nf++) {
                uint32_t rb = st + 2 * GM_TILE +
                              (uint32_t)((nbase + nf * 16 + b_row) * GM_ROWB + koff + b_koff);
                ldsm4(bh[nf], rb);
                if (NPASS == 3) ldsm4(bl[nf], rb + GM_TILE);
            }
#pragma unroll
            for (int mf = 0; mf < 2; mf++)
#pragma unroll
                for (int nf = 0; nf < 4; nf++)
#pragma unroll
                    for (int h = 0; h < 2; h++) {
                        float* a4 = acc[mf][nf * 2 + h];
                        mma16816(a4, ah[mf], bh[nf][h * 2], bh[nf][h * 2 + 1]);
                        if (NPASS == 3)
                            mma16816(a4, ah[mf], bl[nf][h * 2], bl[nf][h * 2 + 1]);
                        mma16816(a4, al[mf], bh[nf][h * 2], bh[nf][h * 2 + 1]);
                    }
        }
        __syncthreads();
    }

    // epilogue
#pragma unroll
    for (int mf = 0; mf < 2; mf++)
#pragma unroll
        for (int nf = 0; nf < 8; nf++) {
            const int row0 = bm + mbase + mf * 16 + (lane >> 2);
            const int col = bn + nbase + nf * 8 + (lane & 3) * 2;
            const float* a4 = acc[mf][nf];
#pragma unroll
            for (int half = 0; half < 2; half++) {
                int row = row0 + half * 8;
                if (row >= M) continue;
                float v0 = a4[half * 2 + 0], v1 = a4[half * 2 + 1];
                if (outmap == 1) {
                    long crow = (long)row + row / TC + 1;
                    *(uint32_t*)(Chi + crow * DD + col) = packh2(v0, v1);
                    *(uint32_t*)(Clo + crow * DD + col) = packh2(hres(v0), hres(v1));
                } else if (outmap == 2) {
                    v0 *= oscale; v1 *= oscale;
                    *(uint32_t*)(Chi + (long)row * DD + col) = packh2(v0, v1);
                    *(uint32_t*)(Clo + (long)row * DD + col) = packh2(hres(v0), hres(v1));
                } else if (outmap == 3) {
                    *(uint32_t*)(Chi + (long)row * DD + col) = packh2(v0, v1);
                } else {
                    if (bias) { v0 += bias[col]; v1 += bias[col + 1]; }
                    *(float2*)(Cf + (long)row * DD + col) = make_float2(v0, v1);
                }
            }
        }
}

// ---------------- mma.sync flash attention (fp16, 2-pass), 3k<=q mask ----------------
// 128 queries/CTA (8 warps x 16 rows), 64-key tiles. K/V single fp16, Q/P split hi/lo.
#define FA_BQ 128
#define FA_BK 64
#define FA_ROWB 144
#define FA_TILE (64 * FA_ROWB)     // 9216
#define FA_STAGE (2 * FA_TILE)     // 18432 : K, V
#define FA_SMEM (2 * FA_STAGE)     // 36864 (also exactly fits Q hi/lo staging)

__global__ void __launch_bounds__(256)
attn_mma(const __half* __restrict__ Qhi, const __half* __restrict__ Qlo,
         const __half* __restrict__ Kg, const __half* __restrict__ Vg,
         __half* __restrict__ Ohi, __half* __restrict__ Olo)
{
    extern __shared__ char smem[];
    const uint32_t sb = smem_u32(smem);
    const int tid = threadIdx.x, wid = tid >> 5, lane = tid & 31;
    const int bh = blockIdx.y, b = bh >> 4, h = bh & 15;
    const int q0 = blockIdx.x * FA_BQ;

    const int grp = lane >> 3, rowg = lane & 7;
    const int a_row = (grp & 1) * 8 + rowg, a_koff = (grp >> 1) * 16;
    const int b_row = (grp >> 1) * 8 + rowg, b_koff = (grp & 1) * 16;
    const int v_row = (grp & 1) * 8 + rowg, v_koff = (grp >> 1) * 16;
    const int lq = lane >> 2, lc = (lane & 3) * 2;
    const int qrow0 = q0 + wid * 16 + lq;
    const int qrow1 = qrow0 + 8;

    // ---- stage Q (hi at 0, lo at +18432), extract fragments ----
#pragma unroll
    for (int it = 0; it < 8; it++) {
        int idx = it * 256 + tid;
        int t = idx >> 10, r = (idx >> 3) & 127, s = idx & 7;
        const __half* src = t ? Qlo : Qhi;
        uint4 v = *(const uint4*)(src + (long)(b * TT + q0 + r) * DD + h * HD + s * 8);
        *(uint4*)(smem + t * 18432 + r * FA_ROWB + s * 16) = v;
    }
    __syncthreads();
    uint32_t qh[4][4], ql[4][4];
#pragma unroll
    for (int ks = 0; ks < 4; ks++) {
        uint32_t ra = sb + (uint32_t)((wid * 16 + a_row) * FA_ROWB + ks * 32 + a_koff);
        ldsm4(qh[ks], ra);
        ldsm4(ql[ks], ra + 18432);
    }
    __syncthreads();

    const int kmax = (q0 + FA_BQ - 1) / 3;
    const int nt = kmax / FA_BK + 1;

    auto load_kv = [&](int stg, int t) {
        const int kt = t * FA_BK;
        const uint32_t dst0 = sb + stg * FA_STAGE;
#pragma unroll
        for (int it = 0; it < 4; it++) {
            int idx = it * 256 + tid;
            int tt = idx >> 9, r = (idx >> 3) & 63, s = idx & 7;
            int kid = kt + r;
            if (kid > TKK - 1) kid = TKK - 1;
            const __half* src = tt ? Vg : Kg;
            const __half* sp = src + (long)(b * TKK + kid) * DD + h * HD + s * 8;
            uint32_t dp = dst0 + (uint32_t)(tt * FA_TILE + r * FA_ROWB + s * 16);
            asm volatile("cp.async.cg.shared.global [%0], [%1], 16;" :: "r"(dp), "l"(sp));
        }
        asm volatile("cp.async.commit_group;" ::: "memory");
    };

    float Oa[8][4];
#pragma unroll
    for (int i = 0; i < 8; i++)
#pragma unroll
        for (int j = 0; j < 4; j++) Oa[i][j] = 0.f;
    float m0 = -1e30f, m1 = -1e30f, l0 = 0.f, l1 = 0.f;

    load_kv(0, 0);

    for (int t = 0; t < nt; t++) {
        const int stg = t & 1;
        if (t + 1 < nt) {
            load_kv(stg ^ 1, t + 1);
            asm volatile("cp.async.wait_group 1;" ::: "memory");
        } else {
            asm volatile("cp.async.wait_group 0;" ::: "memory");
        }
        __syncthreads();

        const int kt = t * FA_BK;
        const uint32_t stk = sb + stg * FA_STAGE;
        const uint32_t stv = stk + FA_TILE;

        // ---- S = Q @ K^T (Q hi/lo, K single) ----
        float S[8][4];
#pragma unroll
        for (int i = 0; i < 8; i++)
#pragma unroll
            for (int j = 0; j < 4; j++) S[i][j] = 0.f;

#pragma unroll
        for (int ng = 0; ng < 4; ng++) {
#pragma unroll
            for (int ks = 0; ks < 4; ks++) {
                uint32_t kh[4];
                uint32_t rb = stk + (uint32_t)((ng * 16 + b_row) * FA_ROWB + ks * 32 + b_koff);
                ldsm4(kh, rb);
                mma16816(S[2 * ng],     qh[ks], kh[0], kh[1]);
                mma16816(S[2 * ng + 1], qh[ks], kh[2], kh[3]);
                mma16816(S[2 * ng],     ql[ks], kh[0], kh[1]);
                mma16816(S[2 * ng + 1], ql[ks], kh[2], kh[3]);
            }
        }

        // ---- mask + online softmax ----
        float mx0 = -1e30f, mx1 = -1e30f;
#pragma unroll
        for (int nf = 0; nf < 8; nf++) {
            int key = kt + nf * 8 + lc;
            if (3 * key > qrow0)       S[nf][0] = -1e30f;
            if (3 * (key + 1) > qrow0) S[nf][1] = -1e30f;
            if (3 * key > qrow1)       S[nf][2] = -1e30f;
            if (3 * (key + 1) > qrow1) S[nf][3] = -1e30f;
            mx0 = fmaxf(mx0, fmaxf(S[nf][0], S[nf][1]));
            mx1 = fmaxf(mx1, fmaxf(S[nf][2], S[nf][3]));
        }
        mx0 = fmaxf(mx0, __shfl_xor_sync(0xFFFFFFFF, mx0, 1));
        mx0 = fmaxf(mx0, __shfl_xor_sync(0xFFFFFFFF, mx0, 2));
        mx1 = fmaxf(mx1, __shfl_xor_sync(0xFFFFFFFF, mx1, 1));
        mx1 = fmaxf(mx1, __shfl_xor_sync(0xFFFFFFFF, mx1, 2));
        float mn0 = fmaxf(m0, mx0), mn1 = fmaxf(m1, mx1);
        float c0 = __expf(m0 - mn0), c1 = __expf(m1 - mn1);

        float ls0 = 0.f, ls1 = 0.f;
#pragma unroll
        for (int nf = 0; nf < 8; nf++) {
            S[nf][0] = __expf(S[nf][0] - mn0);
            S[nf][1] = __expf(S[nf][1] - mn0);
            S[nf][2] = __expf(S[nf][2] - mn1);
            S[nf][3] = __expf(S[nf][3] - mn1);
            ls0 += S[nf][0] + S[nf][1];
            ls1 += S[nf][2] + S[nf][3];
        }
        ls0 += __shfl_xor_sync(0xFFFFFFFF, ls0, 1);
        ls0 += __shfl_xor_sync(0xFFFFFFFF, ls0, 2);
        ls1 += __shfl_xor_sync(0xFFFFFFFF, ls1, 1);
        ls1 += __shfl_xor_sync(0xFFFFFFFF, ls1, 2);
        l0 = l0 * c0 + ls0;
        l1 = l1 * c1 + ls1;
        m0 = mn0; m1 = mn1;

#pragma unroll
        for (int nf = 0; nf < 8; nf++) {
            Oa[nf][0] *= c0; Oa[nf][1] *= c0;
            Oa[nf][2] *= c1; Oa[nf][3] *= c1;
        }

        // ---- O += P @ V (P split hi/lo fp16, V single) ----
#pragma unroll
        for (int g = 0; g < 4; g++) {
            uint32_t ph[4], pl[4];
            float p00 = S[2 * g][0], p01 = S[2 * g][1], p02 = S[2 * g][2], p03 = S[2 * g][3];
            float p10 = S[2 * g + 1][0], p11 = S[2 * g + 1][1], p12 = S[2 * g + 1][2], p13 = S[2 * g + 1][3];
            ph[0] = packh2(p00, p01); ph[1] = packh2(p02, p03);
            ph[2] = packh2(p10, p11); ph[3] = packh2(p12, p13);
            pl[0] = packh2(hres(p00), hres(p01)); pl[1] = packh2(hres(p02), hres(p03));
            pl[2] = packh2(hres(p10), hres(p11)); pl[3] = packh2(hres(p12), hres(p13));
#pragma unroll
            for (int dg = 0; dg < 4; dg++) {
                uint32_t vh[4];
                uint32_t rv = stv + (uint32_t)((g * 16 + v_row) * FA_ROWB + dg * 32 + v_koff);
                ldsm4t(vh, rv);
                mma16816(Oa[2 * dg],     ph, vh[0], vh[1]);
                mma16816(Oa[2 * dg + 1], ph, vh[2], vh[3]);
                mma16816(Oa[2 * dg],     pl, vh[0], vh[1]);
                mma16816(Oa[2 * dg + 1], pl, vh[2], vh[3]);
            }
        }
        __syncthreads();
    }

    // ---- normalize + store fp16 hi/lo ----
    const float inv0 = 1.f / l0, inv1 = 1.f / l1;
#pragma unroll
    for (int nf = 0; nf < 8; nf++) {
#pragma unroll
        for (int r = 0; r < 2; r++) {
            int row = (r == 0) ? qrow0 : qrow1;
            float inv = (r == 0) ? inv0 : inv1;
            float v0 = Oa[nf][r * 2 + 0] * inv;
            float v1 = Oa[nf][r * 2 + 1] * inv;
            long base = (long)(b * TT + row) * DD + h * HD + nf * 8 + lc;
            *(uint32_t*)(Ohi + base) = packh2(v0, v1);
            *(uint32_t*)(Olo + base) = packh2(hres(v0), hres(v1));
        }
    }
}

// ---------------- launch ----------------
extern "C" void kernel_launch(void* const* d_in, const int* in_sizes, int n_in,
                              void* d_out, int out_size)
{
    const float* x     = (const float*)d_in[0];
    const float* Wq    = (const float*)d_in[1];
    const float* Wk    = (const float*)d_in[2];
    const float* Wv    = (const float*)d_in[3];
    const float* Wo    = (const float*)d_in[4];
    const float* bo    = (const float*)d_in[5];
    const float* Wconv = (const float*)d_in[6];
    float* out = (float*)d_out;

    __half *xhi, *xlo, *wqh, *wql, *wkh, *wkl, *wvh, *wvl, *woh, *wol, *wch, *wcl;
    __half *khi, *klo, *qhi, *qlo, *kb, *vb, *ohi, *olo;
    cudaGetSymbolAddress((void**)&xhi, g_xhi);  cudaGetSymbolAddress((void**)&xlo, g_xlo);
    cudaGetSymbolAddress((void**)&wqh, g_wqhi); cudaGetSymbolAddress((void**)&wql, g_wqlo);
    cudaGetSymbolAddress((void**)&wkh, g_wkhi); cudaGetSymbolAddress((void**)&wkl, g_wklo);
    cudaGetSymbolAddress((void**)&wvh, g_wvhi); cudaGetSymbolAddress((void**)&wvl, g_wvlo);
    cudaGetSymbolAddress((void**)&woh, g_wohi); cudaGetSymbolAddress((void**)&wol, g_wolo);
    cudaGetSymbolAddress((void**)&wch, g_wchi); cudaGetSymbolAddress((void**)&wcl, g_wclo);
    cudaGetSymbolAddress((void**)&khi, g_khi2); cudaGetSymbolAddress((void**)&klo, g_klo2);
    cudaGetSymbolAddress((void**)&qhi, g_qhi);  cudaGetSymbolAddress((void**)&qlo, g_qlo);
    cudaGetSymbolAddress((void**)&kb, g_kb);    cudaGetSymbolAddress((void**)&vb, g_vb);
    cudaGetSymbolAddress((void**)&ohi, g_ohi);  cudaGetSymbolAddress((void**)&olo, g_olo);

    cudaFuncSetAttribute(gemm_mma<3>, cudaFuncAttributeMaxDynamicSharedMemorySize, GM_SMEM);
    cudaFuncSetAttribute(gemm_mma<2>, cudaFuncAttributeMaxDynamicSharedMemorySize, GM_SMEM);
    cudaFuncSetAttribute(attn_mma, cudaFuncAttributeMaxDynamicSharedMemorySize, FA_SMEM);

    // conversions (vectorized)
    { int n4 = BB * TT * DD / 4;
      splitv_kernel<<<n4 / 256, 256>>>(x, xhi, xlo, n4); }
    { int n = 4 * (DD * DD / 4);
      split4v_kernel<<<n / 256, 256>>>(Wq, Wk, Wv, Wo,
                                       wqh, wql, wkh, wkl, wvh, wvl, woh, wol); }
    { repack_convv_kernel<<<(DD * 256) / 256, 256>>>(Wconv, wch, wcl); }
    { copy_row0v_kernel<<<(BB * DD / 4) / 256, 256>>>(x, khi, klo); }

    // conv GEMM -> k_tmp (3-pass, scatter, fp16 hi/lo out)
    {
        dim3 grid(DD / GM_BN, (BB * TC + GM_BM - 1) / GM_BM);
        gemm_mma<3><<<grid, 256, GM_SMEM>>>(xhi, xlo, 3L * DD, wch, wcl, nullptr,
                                            nullptr, khi, klo, BB * TC, 3 * DD, 1, 1.f);
    }
    // Q = (x @ Wq^T) * 0.125 (2-pass) -> fp16 hi/lo
    {
        dim3 grid(DD / GM_BN, (BB * TT + GM_BM - 1) / GM_BM);
        gemm_mma<2><<<grid, 256, GM_SMEM>>>(xhi, xlo, (long)DD, wqh, wql, nullptr,
                                            nullptr, qhi, qlo, BB * TT, DD, 2, 0.125f);
    }
    // K, V = k_tmp @ Wk^T / Wv^T (3-pass) -> single fp16
    {
        dim3 grid(DD / GM_BN, (BB * TKK + GM_BM - 1) / GM_BM);
        gemm_mma<3><<<grid, 256, GM_SMEM>>>(khi, klo, (long)DD, wkh, wkl, nullptr,
                                            nullptr, kb, nullptr, BB * TKK, DD, 3, 1.f);
        gemm_mma<3><<<grid, 256, GM_SMEM>>>(khi, klo, (long)DD, wvh, wvl, nullptr,
                                            nullptr, vb, nullptr, BB * TKK, DD, 3, 1.f);
    }
    // attention (2-pass fp16)
    {
        dim3 grid(TT / FA_BQ, BB * HH);                        // (24, 64)
        attn_mma<<<grid, 256, FA_SMEM>>>(qhi, qlo, kb, vb, ohi, olo);
    }
    // out = o @ Wo^T + bo (2-pass)
    {
        dim3 grid(DD / GM_BN, (BB * TT + GM_BM - 1) / GM_BM);
        gemm_mma<2><<<grid, 256, GM_SMEM>>>(ohi, olo, (long)DD, woh, wol, bo,
                                            out, nullptr, nullptr, BB * TT, DD, 0, 1.f);
    }
}

// round 15
// speedup vs baseline: 1.8348x; 1.2081x over previous
#include <cuda_runtime.h>
#include <cuda_fp16.h>
#include <cstdint>
#include <math.h>

// Problem dims
#define BB 4
#define TT 3072
#define DD 1024
#define HH 16
#define HD 64
#define TC 1024          // conv outputs per batch
#define TKK 1025         // k_tmp rows per batch

// ---------------- static scratch (fp16) ----------------
__device__ __half g_xhi[BB * TT * DD], g_xlo[BB * TT * DD];
__device__ __half g_wq[DD * DD];             // weights: single fp16 (B-side of 2-pass)
__device__ __half g_wk[DD * DD];
__device__ __half g_wv[DD * DD];
__device__ __half g_wo[DD * DD];
__device__ __half g_wc[DD * 3 * DD];
__device__ __half g_khi2[BB * TKK * DD], g_klo2[BB * TKK * DD];  // k_tmp hi/lo
__device__ __half g_qhi[BB * TT * DD], g_qlo[BB * TT * DD];      // Q (pre-scaled) hi/lo
__device__ __half g_kb[BB * TKK * DD];                           // K proj (single fp16)
__device__ __half g_vb[BB * TKK * DD];                           // V proj (single fp16)
__device__ __half g_ohi[BB * TT * DD], g_olo[BB * TT * DD];      // attn out hi/lo

// ---------------- helpers ----------------
__device__ __forceinline__ uint32_t smem_u32(const void* p) {
    uint32_t a;
    asm("{ .reg .u64 t; cvta.to.shared.u64 t, %1; cvt.u32.u64 %0, t; }" : "=r"(a) : "l"(p));
    return a;
}
__device__ __forceinline__ void ldsm4(uint32_t* r, uint32_t addr) {
    asm volatile("ldmatrix.sync.aligned.m8n8.x4.shared.b16 {%0,%1,%2,%3}, [%4];"
        : "=r"(r[0]), "=r"(r[1]), "=r"(r[2]), "=r"(r[3]) : "r"(addr));
}
__device__ __forceinline__ void ldsm4t(uint32_t* r, uint32_t addr) {
    asm volatile("ldmatrix.sync.aligned.m8n8.x4.trans.shared.b16 {%0,%1,%2,%3}, [%4];"
        : "=r"(r[0]), "=r"(r[1]), "=r"(r[2]), "=r"(r[3]) : "r"(addr));
}
__device__ __forceinline__ void mma16816(float* c, const uint32_t* a, uint32_t b0, uint32_t b1) {
    asm volatile("mma.sync.aligned.m16n8k16.row.col.f32.f16.f16.f32 "
        "{%0,%1,%2,%3}, {%4,%5,%6,%7}, {%8,%9}, {%0,%1,%2,%3};"
        : "+f"(c[0]), "+f"(c[1]), "+f"(c[2]), "+f"(c[3])
        : "r"(a[0]), "r"(a[1]), "r"(a[2]), "r"(a[3]), "r"(b0), "r"(b1));
}
__device__ __forceinline__ uint32_t packh2(float x, float y) {
    __half2 h = __floats2half2_rn(x, y);
    return *(uint32_t*)&h;
}
__device__ __forceinline__ float hres(float v) {   // v - fp16(v)
    return v - __half2float(__float2half_rn(v));
}

// ---------------- vectorized split / convert kernels ----------------
__global__ void splitv_kernel(const float* __restrict__ s, __half* __restrict__ hi,
                              __half* __restrict__ lo, int n4) {
    int i = blockIdx.x * 256 + threadIdx.x;
    if (i >= n4) return;
    float4 v = ((const float4*)s)[i];
    uint2 H, L;
    H.x = packh2(v.x, v.y);
    H.y = packh2(v.z, v.w);
    L.x = packh2(hres(v.x), hres(v.y));
    L.y = packh2(hres(v.z), hres(v.w));
    ((uint2*)hi)[i] = H;
    ((uint2*)lo)[i] = L;
}
// 4 weight matrices -> single fp16 each
__global__ void cvt4_kernel(const float* __restrict__ w0, const float* __restrict__ w1,
                            const float* __restrict__ w2, const float* __restrict__ w3,
                            __half* __restrict__ h0, __half* __restrict__ h1,
                            __half* __restrict__ h2, __half* __restrict__ h3) {
    int i = blockIdx.x * 256 + threadIdx.x;      // 0 .. 4*(1<<18)-1
    int w = i >> 18, j = i & ((1 << 18) - 1);
    const float* s = (w == 0) ? w0 : (w == 1) ? w1 : (w == 2) ? w2 : w3;
    __half* hp = (w == 0) ? h0 : (w == 1) ? h1 : (w == 2) ? h2 : h3;
    float4 v = ((const float4*)s)[j];
    uint2 H;
    H.x = packh2(v.x, v.y);
    H.y = packh2(v.z, v.w);
    ((uint2*)hp)[j] = H;
}
// conv repack -> single fp16
__global__ void repack_convv_kernel(const float* __restrict__ W, __half* __restrict__ hi) {
    int t = blockIdx.x * 256 + threadIdx.x;      // 0 .. 1024*256-1
    int o = t >> 8;
    int ib = t & 255;                            // i0 = 4*ib
    const float4* src = (const float4*)(W + (long)o * 3072 + ib * 12);
    float4 a = src[0], b4 = src[1], c4 = src[2];
    float w[12] = {a.x, a.y, a.z, a.w, b4.x, b4.y, b4.z, b4.w, c4.x, c4.y, c4.z, c4.w};
#pragma unroll
    for (int kw = 0; kw < 3; kw++) {
        float v0 = w[kw], v1 = w[kw + 3], v2 = w[kw + 6], v3 = w[kw + 9];
        long d = (long)o * 3072 + kw * 1024 + 4 * ib;
        uint2 H;
        H.x = packh2(v0, v1); H.y = packh2(v2, v3);
        *(uint2*)(hi + d) = H;
    }
}
__global__ void copy_row0v_kernel(const float* __restrict__ x, __half* __restrict__ khi,
                                  __half* __restrict__ klo) {
    int i = blockIdx.x * 256 + threadIdx.x;      // 0 .. BB*DD/4-1
    int b = i / (DD / 4), j = i % (DD / 4);
    float4 v = ((const float4*)(x + (long)b * TT * DD))[j];
    uint2 H, L;
    H.x = packh2(v.x, v.y); H.y = packh2(v.z, v.w);
    L.x = packh2(hres(v.x), hres(v.y)); L.y = packh2(hres(v.z), hres(v.w));
    ((uint2*)(khi + (long)b * TKK * DD))[j] = H;
    ((uint2*)(klo + (long)b * TKK * DD))[j] = L;
}

// ---------------- mma.sync GEMM: C[M,1024] = A @ B^T (2-pass one-sided split) ----------------
// (Ahi + Alo) @ Bh^T : two MMA passes, B single fp16.
// outmap 0: fp32 Cf (+bias). 1: conv scatter -> fp16 hi/lo. 2: fp16 hi/lo (scaled). 3: single fp16.
#define GM_BM 128
#define GM_BN 128
#define GM_BK 32
#define GM_ROWB 80
#define GM_TILE (128 * GM_ROWB)        // 10240
#define GM_STAGE (3 * GM_TILE)         // 30720 : Ahi, Alo, Bh
#define GM_SMEM (2 * GM_STAGE)         // 61440

__global__ void __launch_bounds__(256)
gemm_mma(const __half* __restrict__ Ahi, const __half* __restrict__ Alo, long lda,
         const __half* __restrict__ Bh,
         const float* __restrict__ bias,
         float* __restrict__ Cf, __half* __restrict__ Chi, __half* __restrict__ Clo,
         int M, int K, int outmap, float oscale)
{
    extern __shared__ char smem[];
    const uint32_t sb = smem_u32(smem);
    const int tid = threadIdx.x;
    const int wid = tid >> 5, lane = tid & 31;
    const int bm = blockIdx.y * GM_BM, bn = blockIdx.x * GM_BN;
    const int mbase = (wid & 3) * 32;
    const int nbase = (wid >> 2) * 64;

    const int grp = lane >> 3, rowg = lane & 7;
    const int a_row = (grp & 1) * 8 + rowg;
    const int a_koff = (grp >> 1) * 16;
    const int b_row = (grp >> 1) * 8 + rowg;
    const int b_koff = (grp & 1) * 16;

    float acc[2][8][4];
#pragma unroll
    for (int i = 0; i < 2; i++)
#pragma unroll
        for (int j = 0; j < 8; j++)
#pragma unroll
            for (int k = 0; k < 4; k++) acc[i][j][k] = 0.f;

    auto load_stage = [&](int stg, int c) {
        char* base = smem + stg * GM_STAGE;
        const int k0 = c * GM_BK;
#pragma unroll
        for (int it = 0; it < 6; it++) {     // 3 tiles: Ahi, Alo, Bh
            int i = it * 256 + tid;
            int t = i >> 9;
            int r = (i >> 2) & 127;
            int s = i & 3;
            uint4 v = make_uint4(0, 0, 0, 0);
            if (t < 2) {
                int row = bm + r;
                if (row < M) {
                    const __half* src = t ? Alo : Ahi;
                    v = *(const uint4*)(src + (long)row * lda + k0 + s * 8);
                }
            } else {
                v = *(const uint4*)(Bh + (long)(bn + r) * K + k0 + s * 8);
            }
            *(uint4*)(base + t * GM_TILE + r * GM_ROWB + s * 16) = v;
        }
    };

    const int nch = K / GM_BK;
    load_stage(0, 0);
    __syncthreads();

    for (int c = 0; c < nch; c++) {
        const uint32_t st = sb + (c & 1) * GM_STAGE;
        if (c + 1 < nch) load_stage((c + 1) & 1, c + 1);
#pragma unroll
        for (int ks = 0; ks < 2; ks++) {
            const int koff = ks * 32;
            uint32_t ah[2][4], al[2][4];
#pragma unroll
            for (int mf = 0; mf < 2; mf++) {
                uint32_t ra = st + (uint32_t)((mbase + mf * 16 + a_row) * GM_ROWB + koff + a_koff);
                ldsm4(ah[mf], ra);
                ldsm4(al[mf], ra + GM_TILE);
            }
            uint32_t bh[4][4];
#pragma unroll
            for (int nf = 0; nf < 4; nf++) {
                uint32_t rb = st + 2 * GM_TILE +
                              (uint32_t)((nbase + nf * 16 + b_row) * GM_ROWB + koff + b_koff);
                ldsm4(bh[nf], rb);
            }
#pragma unroll
            for (int mf = 0; mf < 2; mf++)
#pragma unroll
                for (int nf = 0; nf < 4; nf++)
#pragma unroll
                    for (int h = 0; h < 2; h++) {
                        float* a4 = acc[mf][nf * 2 + h];
                        mma16816(a4, ah[mf], bh[nf][h * 2], bh[nf][h * 2 + 1]);
                        mma16816(a4, al[mf], bh[nf][h * 2], bh[nf][h * 2 + 1]);
                    }
        }
        __syncthreads();
    }

    // epilogue
#pragma unroll
    for (int mf = 0; mf < 2; mf++)
#pragma unroll
        for (int nf = 0; nf < 8; nf++) {
            const int row0 = bm + mbase + mf * 16 + (lane >> 2);
            const int col = bn + nbase + nf * 8 + (lane & 3) * 2;
            const float* a4 = acc[mf][nf];
#pragma unroll
            for (int half = 0; half < 2; half++) {
                int row = row0 + half * 8;
                if (row >= M) continue;
                float v0 = a4[half * 2 + 0], v1 = a4[half * 2 + 1];
                if (outmap == 1) {
                    long crow = (long)row + row / TC + 1;
                    *(uint32_t*)(Chi + crow * DD + col) = packh2(v0, v1);
                    *(uint32_t*)(Clo + crow * DD + col) = packh2(hres(v0), hres(v1));
                } else if (outmap == 2) {
                    v0 *= oscale; v1 *= oscale;
                    *(uint32_t*)(Chi + (long)row * DD + col) = packh2(v0, v1);
                    *(uint32_t*)(Clo + (long)row * DD + col) = packh2(hres(v0), hres(v1));
                } else if (outmap == 3) {
                    *(uint32_t*)(Chi + (long)row * DD + col) = packh2(v0, v1);
                } else {
                    if (bias) { v0 += bias[col]; v1 += bias[col + 1]; }
                    *(float2*)(Cf + (long)row * DD + col) = make_float2(v0, v1);
                }
            }
        }
}

// ---------------- mma.sync flash attention (fp16), 3k<=q mask ----------------
// QK: Q hi/lo x K single (2-pass).  PV: P single x V single (1-pass).
#define FA_BQ 128
#define FA_BK 64
#define FA_ROWB 144
#define FA_TILE (64 * FA_ROWB)     // 9216
#define FA_STAGE (2 * FA_TILE)     // 18432 : K, V
#define FA_SMEM (2 * FA_STAGE)     // 36864 (also exactly fits Q hi/lo staging)

__global__ void __launch_bounds__(256)
attn_mma(const __half* __restrict__ Qhi, const __half* __restrict__ Qlo,
         const __half* __restrict__ Kg, const __half* __restrict__ Vg,
         __half* __restrict__ Ohi, __half* __restrict__ Olo)
{
    extern __shared__ char smem[];
    const uint32_t sb = smem_u32(smem);
    const int tid = threadIdx.x, wid = tid >> 5, lane = tid & 31;
    const int bh = blockIdx.y, b = bh >> 4, h = bh & 15;
    const int q0 = blockIdx.x * FA_BQ;

    const int grp = lane >> 3, rowg = lane & 7;
    const int a_row = (grp & 1) * 8 + rowg, a_koff = (grp >> 1) * 16;
    const int b_row = (grp >> 1) * 8 + rowg, b_koff = (grp & 1) * 16;
    const int v_row = (grp & 1) * 8 + rowg, v_koff = (grp >> 1) * 16;
    const int lq = lane >> 2, lc = (lane & 3) * 2;
    const int qrow0 = q0 + wid * 16 + lq;
    const int qrow1 = qrow0 + 8;

    // ---- stage Q (hi at 0, lo at +18432), extract fragments ----
#pragma unroll
    for (int it = 0; it < 8; it++) {
        int idx = it * 256 + tid;
        int t = idx >> 10, r = (idx >> 3) & 127, s = idx & 7;
        const __half* src = t ? Qlo : Qhi;
        uint4 v = *(const uint4*)(src + (long)(b * TT + q0 + r) * DD + h * HD + s * 8);
        *(uint4*)(smem + t * 18432 + r * FA_ROWB + s * 16) = v;
    }
    __syncthreads();
    uint32_t qh[4][4], ql[4][4];
#pragma unroll
    for (int ks = 0; ks < 4; ks++) {
        uint32_t ra = sb + (uint32_t)((wid * 16 + a_row) * FA_ROWB + ks * 32 + a_koff);
        ldsm4(qh[ks], ra);
        ldsm4(ql[ks], ra + 18432);
    }
    __syncthreads();

    const int kmax = (q0 + FA_BQ - 1) / 3;
    const int nt = kmax / FA_BK + 1;

    auto load_kv = [&](int stg, int t) {
        const int kt = t * FA_BK;
        const uint32_t dst0 = sb + stg * FA_STAGE;
#pragma unroll
        for (int it = 0; it < 4; it++) {
            int idx = it * 256 + tid;
            int tt = idx >> 9, r = (idx >> 3) & 63, s = idx & 7;
            int kid = kt + r;
            if (kid > TKK - 1) kid = TKK - 1;
            const __half* src = tt ? Vg : Kg;
            const __half* sp = src + (long)(b * TKK + kid) * DD + h * HD + s * 8;
            uint32_t dp = dst0 + (uint32_t)(tt * FA_TILE + r * FA_ROWB + s * 16);
            asm volatile("cp.async.cg.shared.global [%0], [%1], 16;" :: "r"(dp), "l"(sp));
        }
        asm volatile("cp.async.commit_group;" ::: "memory");
    };

    float Oa[8][4];
#pragma unroll
    for (int i = 0; i < 8; i++)
#pragma unroll
        for (int j = 0; j < 4; j++) Oa[i][j] = 0.f;
    float m0 = -1e30f, m1 = -1e30f, l0 = 0.f, l1 = 0.f;

    load_kv(0, 0);

    for (int t = 0; t < nt; t++) {
        const int stg = t & 1;
        if (t + 1 < nt) {
            load_kv(stg ^ 1, t + 1);
            asm volatile("cp.async.wait_group 1;" ::: "memory");
        } else {
            asm volatile("cp.async.wait_group 0;" ::: "memory");
        }
        __syncthreads();

        const int kt = t * FA_BK;
        const uint32_t stk = sb + stg * FA_STAGE;
        const uint32_t stv = stk + FA_TILE;

        // ---- S = Q @ K^T (Q hi/lo, K single) ----
        float S[8][4];
#pragma unroll
        for (int i = 0; i < 8; i++)
#pragma unroll
            for (int j = 0; j < 4; j++) S[i][j] = 0.f;

#pragma unroll
        for (int ng = 0; ng < 4; ng++) {
#pragma unroll
            for (int ks = 0; ks < 4; ks++) {
                uint32_t kh[4];
                uint32_t rb = stk + (uint32_t)((ng * 16 + b_row) * FA_ROWB + ks * 32 + b_koff);
                ldsm4(kh, rb);
                mma16816(S[2 * ng],     qh[ks], kh[0], kh[1]);
                mma16816(S[2 * ng + 1], qh[ks], kh[2], kh[3]);
                mma16816(S[2 * ng],     ql[ks], kh[0], kh[1]);
                mma16816(S[2 * ng + 1], ql[ks], kh[2], kh[3]);
            }
        }

        // ---- mask + online softmax ----
        float mx0 = -1e30f, mx1 = -1e30f;
#pragma unroll
        for (int nf = 0; nf < 8; nf++) {
            int key = kt + nf * 8 + lc;
            if (3 * key > qrow0)       S[nf][0] = -1e30f;
            if (3 * (key + 1) > qrow0) S[nf][1] = -1e30f;
            if (3 * key > qrow1)       S[nf][2] = -1e30f;
            if (3 * (key + 1) > qrow1) S[nf][3] = -1e30f;
            mx0 = fmaxf(mx0, fmaxf(S[nf][0], S[nf][1]));
            mx1 = fmaxf(mx1, fmaxf(S[nf][2], S[nf][3]));
        }
        mx0 = fmaxf(mx0, __shfl_xor_sync(0xFFFFFFFF, mx0, 1));
        mx0 = fmaxf(mx0, __shfl_xor_sync(0xFFFFFFFF, mx0, 2));
        mx1 = fmaxf(mx1, __shfl_xor_sync(0xFFFFFFFF, mx1, 1));
        mx1 = fmaxf(mx1, __shfl_xor_sync(0xFFFFFFFF, mx1, 2));
        float mn0 = fmaxf(m0, mx0), mn1 = fmaxf(m1, mx1);
        float c0 = __expf(m0 - mn0), c1 = __expf(m1 - mn1);

        float ls0 = 0.f, ls1 = 0.f;
#pragma unroll
        for (int nf = 0; nf < 8; nf++) {
            S[nf][0] = __expf(S[nf][0] - mn0);
            S[nf][1] = __expf(S[nf][1] - mn0);
            S[nf][2] = __expf(S[nf][2] - mn1);
            S[nf][3] = __expf(S[nf][3] - mn1);
            ls0 += S[nf][0] + S[nf][1];
            ls1 += S[nf][2] + S[nf][3];
        }
        ls0 += __shfl_xor_sync(0xFFFFFFFF, ls0, 1);
        ls0 += __shfl_xor_sync(0xFFFFFFFF, ls0, 2);
        ls1 += __shfl_xor_sync(0xFFFFFFFF, ls1, 1);
        ls1 += __shfl_xor_sync(0xFFFFFFFF, ls1, 2);
        l0 = l0 * c0 + ls0;
        l1 = l1 * c1 + ls1;
        m0 = mn0; m1 = mn1;

#pragma unroll
        for (int nf = 0; nf < 8; nf++) {
            Oa[nf][0] *= c0; Oa[nf][1] *= c0;
            Oa[nf][2] *= c1; Oa[nf][3] *= c1;
        }

        // ---- O += P @ V (P single fp16, V single) ----
#pragma unroll
        for (int g = 0; g < 4; g++) {
            uint32_t ph[4];
            ph[0] = packh2(S[2 * g][0], S[2 * g][1]);
            ph[1] = packh2(S[2 * g][2], S[2 * g][3]);
            ph[2] = packh2(S[2 * g + 1][0], S[2 * g + 1][1]);
            ph[3] = packh2(S[2 * g + 1][2], S[2 * g + 1][3]);
#pragma unroll
            for (int dg = 0; dg < 4; dg++) {
                uint32_t vh[4];
                uint32_t rv = stv + (uint32_t)((g * 16 + v_row) * FA_ROWB + dg * 32 + v_koff);
                ldsm4t(vh, rv);
                mma16816(Oa[2 * dg],     ph, vh[0], vh[1]);
                mma16816(Oa[2 * dg + 1], ph, vh[2], vh[3]);
            }
        }
        __syncthreads();
    }

    // ---- normalize + store fp16 hi/lo ----
    const float inv0 = 1.f / l0, inv1 = 1.f / l1;
#pragma unroll
    for (int nf = 0; nf < 8; nf++) {
#pragma unroll
        for (int r = 0; r < 2; r++) {
            int row = (r == 0) ? qrow0 : qrow1;
            float inv = (r == 0) ? inv0 : inv1;
            float v0 = Oa[nf][r * 2 + 0] * inv;
            float v1 = Oa[nf][r * 2 + 1] * inv;
            long base = (long)(b * TT + row) * DD + h * HD + nf * 8 + lc;
            *(uint32_t*)(Ohi + base) = packh2(v0, v1);
            *(uint32_t*)(Olo + base) = packh2(hres(v0), hres(v1));
        }
    }
}

// ---------------- launch ----------------
extern "C" void kernel_launch(void* const* d_in, const int* in_sizes, int n_in,
                              void* d_out, int out_size)
{
    const float* x     = (const float*)d_in[0];
    const float* Wq    = (const float*)d_in[1];
    const float* Wk    = (const float*)d_in[2];
    const float* Wv    = (const float*)d_in[3];
    const float* Wo    = (const float*)d_in[4];
    const float* bo    = (const float*)d_in[5];
    const float* Wconv = (const float*)d_in[6];
    float* out = (float*)d_out;

    __half *xhi, *xlo, *wq, *wk, *wv, *wo, *wc;
    __half *khi, *klo, *qhi, *qlo, *kb, *vb, *ohi, *olo;
    cudaGetSymbolAddress((void**)&xhi, g_xhi);  cudaGetSymbolAddress((void**)&xlo, g_xlo);
    cudaGetSymbolAddress((void**)&wq, g_wq);
    cudaGetSymbolAddress((void**)&wk, g_wk);
    cudaGetSymbolAddress((void**)&wv, g_wv);
    cudaGetSymbolAddress((void**)&wo, g_wo);
    cudaGetSymbolAddress((void**)&wc, g_wc);
    cudaGetSymbolAddress((void**)&khi, g_khi2); cudaGetSymbolAddress((void**)&klo, g_klo2);
    cudaGetSymbolAddress((void**)&qhi, g_qhi);  cudaGetSymbolAddress((void**)&qlo, g_qlo);
    cudaGetSymbolAddress((void**)&kb, g_kb);    cudaGetSymbolAddress((void**)&vb, g_vb);
    cudaGetSymbolAddress((void**)&ohi, g_ohi);  cudaGetSymbolAddress((void**)&olo, g_olo);

    cudaFuncSetAttribute(gemm_mma, cudaFuncAttributeMaxDynamicSharedMemorySize, GM_SMEM);
    cudaFuncSetAttribute(attn_mma, cudaFuncAttributeMaxDynamicSharedMemorySize, FA_SMEM);

    // conversions (vectorized)
    { int n4 = BB * TT * DD / 4;
      splitv_kernel<<<n4 / 256, 256>>>(x, xhi, xlo, n4); }
    { int n = 4 * (DD * DD / 4);
      cvt4_kernel<<<n / 256, 256>>>(Wq, Wk, Wv, Wo, wq, wk, wv, wo); }
    { repack_convv_kernel<<<(DD * 256) / 256, 256>>>(Wconv, wc); }
    { copy_row0v_kernel<<<(BB * DD / 4) / 256, 256>>>(x, khi, klo); }

    // conv GEMM -> k_tmp (2-pass, scatter, fp16 hi/lo out)
    {
        dim3 grid(DD / GM_BN, (BB * TC + GM_BM - 1) / GM_BM);
        gemm_mma<<<grid, 256, GM_SMEM>>>(xhi, xlo, 3L * DD, wc, nullptr,
                                         nullptr, khi, klo, BB * TC, 3 * DD, 1, 1.f);
    }
    // Q = (x @ Wq^T) * 0.125 (2-pass) -> fp16 hi/lo
    {
        dim3 grid(DD / GM_BN, (BB * TT + GM_BM - 1) / GM_BM);
        gemm_mma<<<grid, 256, GM_SMEM>>>(xhi, xlo, (long)DD, wq, nullptr,
                                         nullptr, qhi, qlo, BB * TT, DD, 2, 0.125f);
    }
    // K, V = k_tmp @ Wk^T / Wv^T (2-pass) -> single fp16
    {
        dim3 grid(DD / GM_BN, (BB * TKK + GM_BM - 1) / GM_BM);
        gemm_mma<<<grid, 256, GM_SMEM>>>(khi, klo, (long)DD, wk, nullptr,
                                         nullptr, kb, nullptr, BB * TKK, DD, 3, 1.f);
        gemm_mma<<<grid, 256, GM_SMEM>>>(khi, klo, (long)DD, wv, nullptr,
                                         nullptr, vb, nullptr, BB * TKK, DD, 3, 1.f);
    }
    // attention (QK 2-pass, PV 1-pass)
    {
        dim3 grid(TT / FA_BQ, BB * HH);                        // (24, 64)
        attn_mma<<<grid, 256, FA_SMEM>>>(qhi, qlo, kb, vb, ohi, olo);
    }
    // out = o @ Wo^T + bo (2-pass)
    {
        dim3 grid(DD / GM_BN, (BB * TT + GM_BM - 1) / GM_BM);
        gemm_mma<<<grid, 256, GM_SMEM>>>(ohi, olo, (long)DD, wo, bo,
                                         out, nullptr, nullptr, BB * TT, DD, 0, 1.f);
    }
}